// round 12
// baseline (speedup 1.0000x reference)
#include <cuda_runtime.h>
#include <cuda_fp16.h>
#include <math.h>
#include <stdint.h>

// ---------------- constants ----------------
#define MROWS  100352      // 32 * 3136
#define CDIM   192
#define NHEADS 6
#define KD     32
#define QKVN   576
#define HID    768
#define HW     56

// transposed fp16 weight scratch offsets (all [N,K] K-major)
#define W_QKV  0
#define W_PROJ 110592
#define W_FC1  147456
#define W_FC2  294912
#define W_TOT  442368

// ---------------- scratch ----------------
__device__ __half g_ln  [(size_t)MROWS * CDIM];   // LN2 output (MLP input)
__device__ __half g_qkv [(size_t)MROWS * QKVN];
__device__ __half g_attn[(size_t)MROWS * CDIM];
__device__ float  g_x1  [(size_t)MROWS * CDIM];
__device__ float  g_x2  [(size_t)MROWS * CDIM];
__device__ __half g_wt  [W_TOT];

// ---------------- helpers ----------------
__device__ __forceinline__ uint32_t smem_u32(const void* p) {
    uint32_t a;
    asm("{ .reg .u64 t; cvta.to.shared.u64 t, %1; cvt.u32.u64 %0, t; }" : "=r"(a) : "l"(p));
    return a;
}

__device__ __forceinline__ void cp16s(uint32_t s, const void* g) {
    asm volatile("cp.async.ca.shared.global [%0], [%1], 16;" :: "r"(s), "l"(g));
}

__device__ __forceinline__ void ldsm4(uint32_t* r, uint32_t addr) {
    asm volatile("ldmatrix.sync.aligned.m8n8.x4.shared.b16 {%0,%1,%2,%3}, [%4];"
                 : "=r"(r[0]), "=r"(r[1]), "=r"(r[2]), "=r"(r[3]) : "r"(addr));
}

__device__ __forceinline__ void ldsm4t(uint32_t* r, uint32_t addr) {
    asm volatile("ldmatrix.sync.aligned.m8n8.x4.trans.shared.b16 {%0,%1,%2,%3}, [%4];"
                 : "=r"(r[0]), "=r"(r[1]), "=r"(r[2]), "=r"(r[3]) : "r"(addr));
}

__device__ __forceinline__ void mma_f16(float* d, const uint32_t* a, const uint32_t* b) {
    asm volatile(
        "mma.sync.aligned.m16n8k16.row.col.f32.f16.f16.f32 "
        "{%0,%1,%2,%3}, {%4,%5,%6,%7}, {%8,%9}, {%0,%1,%2,%3};"
        : "+f"(d[0]), "+f"(d[1]), "+f"(d[2]), "+f"(d[3])
        : "r"(a[0]), "r"(a[1]), "r"(a[2]), "r"(a[3]), "r"(b[0]), "r"(b[1]));
}

// ---------------- merged weight transpose: 4 tensors in one launch ----------------
__global__ void __launch_bounds__(256) transpose_all(const float* __restrict__ qkv_w,
                                                     const float* __restrict__ proj_w,
                                                     const float* __restrict__ fc1_w,
                                                     const float* __restrict__ fc2_w,
                                                     __half* __restrict__ wt)
{
    __shared__ float t[32][33];
    int bid = blockIdx.x;
    const float* src; __half* dst; int Kdim, Ndim, bx, by;
    if (bid < 108)      { src = qkv_w;  dst = wt + W_QKV;  Kdim = CDIM; Ndim = QKVN; int q = bid;       bx = q % 18; by = q / 18; }
    else if (bid < 144) { src = proj_w; dst = wt + W_PROJ; Kdim = CDIM; Ndim = CDIM; int q = bid - 108; bx = q % 6;  by = q / 6; }
    else if (bid < 288) { src = fc1_w;  dst = wt + W_FC1;  Kdim = CDIM; Ndim = HID;  int q = bid - 144; bx = q % 24; by = q / 24; }
    else                { src = fc2_w;  dst = wt + W_FC2;  Kdim = HID;  Ndim = CDIM; int q = bid - 288; bx = q % 6;  by = q / 6; }

    int n0 = bx * 32, k0 = by * 32;
    int tx = threadIdx.x & 31, ty = threadIdx.x >> 5;
#pragma unroll
    for (int i = ty; i < 32; i += 8)
        t[i][tx] = src[(size_t)(k0 + i) * Ndim + n0 + tx];
    __syncthreads();
#pragma unroll
    for (int i = ty; i < 32; i += 8)
        dst[(size_t)(n0 + i) * Kdim + k0 + tx] = __float2half(t[tx][i]);
}

// ---------------- fused LN1 + QKV GEMM ----------------
// grid (1568, 3), 256 thr, BM=64, BN=192, K=192 (all in smem, no ring).
// LN: 4 threads/row, quad shuffle reduction, normalized fp16 -> swizzled A tile.
#define QL_A    0                // 3 chunks x 8192
#define QL_B    24576            // 3 chunks x 24576
#define QL_SMEM 98304            // 96KB -> 2 CTAs/SM

__global__ void __launch_bounds__(256, 2) qkv_ln_gemm(const float* __restrict__ x,
                                                      const __half* __restrict__ BT,
                                                      const float* __restrict__ bias,
                                                      const float* __restrict__ g1,
                                                      const float* __restrict__ b1,
                                                      __half* __restrict__ Cout)
{
    extern __shared__ char smem[];
    const uint32_t sb = smem_u32(smem);

    const int tid  = threadIdx.x;
    const int wid  = tid >> 5, lane = tid & 31;
    const int wm   = wid & 1,  wn   = wid >> 1;
    const int g    = lane >> 2, t4  = lane & 3;
    const int lg   = lane >> 3, lr  = lane & 7;
    const long m0  = (long)blockIdx.x * 64;
    const int  n0  = blockIdx.y * 192;

    // B loads: 3 chunks, one cp.async group (overlaps the LN math below)
#pragma unroll
    for (int c = 0; c < 3; c++)
#pragma unroll
        for (int i = 0; i < 6; i++) {
            int q = tid + i * 256;
            int row = q >> 3, u = q & 7;
            cp16s(sb + QL_B + (uint32_t)c * 24576 + (uint32_t)row * 128 +
                      (uint32_t)((u ^ (row & 7)) * 16),
                  BT + (size_t)(n0 + row) * CDIM + c * 64 + u * 8);
        }
    asm volatile("cp.async.commit_group;");

    // ---- LN1 for this block's 64 rows ----
    {
        const int row = tid >> 2, seg = tid & 3;       // 4 threads per row, 48 cols each
        const float* xr = x + (m0 + row) * (size_t)CDIM + seg * 48;
        float fv[48];
#pragma unroll
        for (int i = 0; i < 12; i++) {
            float4 v = __ldg((const float4*)xr + i);
            fv[4 * i] = v.x; fv[4 * i + 1] = v.y; fv[4 * i + 2] = v.z; fv[4 * i + 3] = v.w;
        }
        float s = 0.f, sq = 0.f;
#pragma unroll
        for (int i = 0; i < 48; i++) { s += fv[i]; sq += fv[i] * fv[i]; }
        s  += __shfl_xor_sync(0xffffffffu, s, 1);  s  += __shfl_xor_sync(0xffffffffu, s, 2);
        sq += __shfl_xor_sync(0xffffffffu, sq, 1); sq += __shfl_xor_sync(0xffffffffu, sq, 2);
        const float mean = s * (1.0f / 192.0f);
        const float var  = sq * (1.0f / 192.0f) - mean * mean;
        const float rstd = rsqrtf(var + 1e-5f);

        const float* gp = g1 + seg * 48;
        const float* bp = b1 + seg * 48;
#pragma unroll
        for (int u = 0; u < 6; u++) {
            uint32_t pk[4];
#pragma unroll
            for (int h = 0; h < 4; h++) {
                int e = u * 8 + 2 * h;
                float o0 = (fv[e]     - mean) * rstd * __ldg(gp + e)     + __ldg(bp + e);
                float o1 = (fv[e + 1] - mean) * rstd * __ldg(gp + e + 1) + __ldg(bp + e + 1);
                __half2 hv = __floats2half2_rn(o0, o1);
                pk[h] = *(uint32_t*)&hv;
            }
            int cb = seg * 48 + u * 8;
            int chunk = cb >> 6, uc = (cb & 63) >> 3;
            uint32_t addr = sb + QL_A + (uint32_t)chunk * 8192 + (uint32_t)row * 128 +
                            (uint32_t)((uc ^ (row & 7)) << 4);
            asm volatile("st.shared.v4.b32 [%0], {%1,%2,%3,%4};"
                         :: "r"(addr), "r"(pk[0]), "r"(pk[1]), "r"(pk[2]), "r"(pk[3]));
        }
    }
    asm volatile("cp.async.wait_group 0;");
    __syncthreads();

    // ---- mma mainloop: 3 chunks x 4 k16-steps ----
    float acc[2][6][4];
#pragma unroll
    for (int mi = 0; mi < 2; mi++)
#pragma unroll
        for (int nj = 0; nj < 6; nj++)
#pragma unroll
            for (int r = 0; r < 4; r++) acc[mi][nj][r] = 0.f;

    uint32_t pA[2], xA[2];
#pragma unroll
    for (int mi = 0; mi < 2; mi++) {
        int row = wm * 32 + mi * 16 + (lg & 1) * 8 + lr;
        pA[mi] = (uint32_t)row * 128;
        xA[mi] = (uint32_t)(row & 7) * 16;
    }
    const uint32_t hiA = (uint32_t)(lg >> 1) * 16;
    uint32_t pB[3], xB[3];
#pragma unroll
    for (int p = 0; p < 3; p++) {
        int row = wn * 48 + p * 16 + ((lg >> 1) & 1) * 8 + lr;
        pB[p] = (uint32_t)row * 128;
        xB[p] = (uint32_t)(row & 7) * 16;
    }
    const uint32_t hiB = (uint32_t)(lg & 1) * 16;

#pragma unroll
    for (int c = 0; c < 3; c++) {
        const uint32_t sa  = sb + QL_A + (uint32_t)c * 8192;
        const uint32_t sbB = sb + QL_B + (uint32_t)c * 24576;
#pragma unroll
        for (int s = 0; s < 4; s++) {
            const uint32_t cs = (uint32_t)(s * 32);
            uint32_t a[2][4], b[6][2];
#pragma unroll
            for (int mi = 0; mi < 2; mi++)
                ldsm4(a[mi], sa + pA[mi] + ((cs + hiA) ^ xA[mi]));
#pragma unroll
            for (int p = 0; p < 3; p++) {
                uint32_t r[4];
                ldsm4(r, sbB + pB[p] + ((cs + hiB) ^ xB[p]));
                b[2 * p][0]     = r[0]; b[2 * p][1]     = r[1];
                b[2 * p + 1][0] = r[2]; b[2 * p + 1][1] = r[3];
            }
#pragma unroll
            for (int mi = 0; mi < 2; mi++)
#pragma unroll
                for (int nj = 0; nj < 6; nj++)
                    mma_f16(acc[mi][nj], a[mi], b[nj]);
        }
    }

    // epilogue: bias -> fp16
#pragma unroll
    for (int mi = 0; mi < 2; mi++) {
#pragma unroll
        for (int half = 0; half < 2; half++) {
            long r = m0 + wm * 32 + mi * 16 + g + half * 8;
#pragma unroll
            for (int nj = 0; nj < 6; nj++) {
                int cb = n0 + wn * 48 + nj * 8 + 2 * t4;
                float o0 = acc[mi][nj][half * 2 + 0] + __ldg(bias + cb);
                float o1 = acc[mi][nj][half * 2 + 1] + __ldg(bias + cb + 1);
                __half2 hv = __floats2half2_rn(o0, o1);
                *(__half2*)(Cout + r * (size_t)QKVN + cb) = hv;
            }
        }
    }
}

// ---------------- FP16 mma GEMM (proj): BM=64, BN=192, BK=64, 3-stage, 1 sync/iter ----
#define GT_BOFF  8192
#define GT_STAGE 32768
#define GT_SMEM  (3 * GT_STAGE)

template <int EPI>
__global__ void __launch_bounds__(256, 2) gemm_h(const __half* __restrict__ A,
                                                 const __half* __restrict__ BT,
                                                 const float* __restrict__ bias,
                                                 const float* __restrict__ res,
                                                 void* __restrict__ Cout,
                                                 int N, int K)
{
    extern __shared__ char smem[];
    const uint32_t sb = smem_u32(smem);

    const int tid  = threadIdx.x;
    const int wid  = tid >> 5, lane = tid & 31;
    const int wm   = wid & 1,  wn   = wid >> 1;
    const int g    = lane >> 2, t4  = lane & 3;
    const int lg   = lane >> 3, lr  = lane & 7;
    const long m0  = (long)blockIdx.x * 64;
    const int  n0  = blockIdx.y * 192;
    const int  T   = K >> 6;

    float acc[2][6][4];
#pragma unroll
    for (int mi = 0; mi < 2; mi++)
#pragma unroll
        for (int nj = 0; nj < 6; nj++)
#pragma unroll
            for (int r = 0; r < 4; r++) acc[mi][nj][r] = 0.f;

    uint32_t pA[2], xA[2];
#pragma unroll
    for (int mi = 0; mi < 2; mi++) {
        int row = wm * 32 + mi * 16 + (lg & 1) * 8 + lr;
        pA[mi] = (uint32_t)row * 128;
        xA[mi] = (uint32_t)(row & 7) * 16;
    }
    const uint32_t hiA = (uint32_t)(lg >> 1) * 16;
    uint32_t pB[3], xB[3];
#pragma unroll
    for (int p = 0; p < 3; p++) {
        int row = wn * 48 + p * 16 + ((lg >> 1) & 1) * 8 + lr;
        pB[p] = (uint32_t)row * 128;
        xB[p] = (uint32_t)(row & 7) * 16;
    }
    const uint32_t hiB = (uint32_t)(lg & 1) * 16;

    auto load_stage = [&](int t, int st) {
        const uint32_t sa = sb + (uint32_t)st * GT_STAGE;
        const int kf = t << 6;
#pragma unroll
        for (int i = 0; i < 2; i++) {
            int q = tid + i * 256;
            int row = q >> 3, ch = q & 7;
            cp16s(sa + (uint32_t)row * 128 + (uint32_t)((ch ^ (row & 7)) * 16),
                  A + (m0 + row) * (size_t)K + kf + ch * 8);
        }
#pragma unroll
        for (int i = 0; i < 6; i++) {
            int q = tid + i * 256;
            int row = q >> 3, ch = q & 7;
            cp16s(sa + GT_BOFF + (uint32_t)row * 128 + (uint32_t)((ch ^ (row & 7)) * 16),
                  BT + (size_t)(n0 + row) * K + kf + ch * 8);
        }
    };

    load_stage(0, 0);
    asm volatile("cp.async.commit_group;");
    load_stage(1, 1);
    asm volatile("cp.async.commit_group;");

    for (int t = 0; t < T; t++) {
        // single sync per iter: load(t+2) writes slot (t+2)%3, last read at compute(t-1),
        // which completed before this barrier for all threads.
        if (t == T - 1) asm volatile("cp.async.wait_group 0;");
        else            asm volatile("cp.async.wait_group 1;");
        __syncthreads();
        if (t + 2 < T) {
            load_stage(t + 2, (t + 2) % 3);
            asm volatile("cp.async.commit_group;");
        }

        const uint32_t sa  = sb + (uint32_t)(t % 3) * GT_STAGE;
        const uint32_t sbB = sa + GT_BOFF;
#pragma unroll
        for (int s = 0; s < 4; s++) {
            const uint32_t cs = (uint32_t)(s * 32);
            uint32_t a[2][4], b[6][2];
#pragma unroll
            for (int mi = 0; mi < 2; mi++)
                ldsm4(a[mi], sa + pA[mi] + ((cs + hiA) ^ xA[mi]));
#pragma unroll
            for (int p = 0; p < 3; p++) {
                uint32_t r[4];
                ldsm4(r, sbB + pB[p] + ((cs + hiB) ^ xB[p]));
                b[2 * p][0]     = r[0]; b[2 * p][1]     = r[1];
                b[2 * p + 1][0] = r[2]; b[2 * p + 1][1] = r[3];
            }
#pragma unroll
            for (int mi = 0; mi < 2; mi++)
#pragma unroll
                for (int nj = 0; nj < 6; nj++)
                    mma_f16(acc[mi][nj], a[mi], b[nj]);
        }
    }

#pragma unroll
    for (int mi = 0; mi < 2; mi++) {
#pragma unroll
        for (int half = 0; half < 2; half++) {
            long r = m0 + wm * 32 + mi * 16 + g + half * 8;
#pragma unroll
            for (int nj = 0; nj < 6; nj++) {
                int cb = n0 + wn * 48 + nj * 8 + 2 * t4;
                float o0 = acc[mi][nj][half * 2 + 0] + __ldg(bias + cb);
                float o1 = acc[mi][nj][half * 2 + 1] + __ldg(bias + cb + 1);
                if (EPI == 1) {
                    o0 = 0.5f * o0 * (1.0f + erff(o0 * 0.7071067811865476f));
                    o1 = 0.5f * o1 * (1.0f + erff(o1 * 0.7071067811865476f));
                }
                if (EPI == 2) {
                    const float2 rv = *(const float2*)(res + r * (size_t)N + cb);
                    o0 += rv.x; o1 += rv.y;
                    *(float2*)((float*)Cout + r * (size_t)N + cb) = make_float2(o0, o1);
                } else {
                    __half2 hv = __floats2half2_rn(o0, o1);
                    *(__half2*)((__half*)Cout + r * (size_t)N + cb) = hv;
                }
            }
        }
    }
}

// ---------------- fused MLP: out = x2 + fc2(gelu(fc1(ln2))) ----------------
#define MF_A    0
#define MF_H    24576
#define MF_RING 49152
#define MF_SMEM 98304

__global__ void __launch_bounds__(256, 2) mlp_fused(const __half* __restrict__ A,
                                                    const __half* __restrict__ W1T,
                                                    const __half* __restrict__ W2T,
                                                    const float* __restrict__ b1,
                                                    const float* __restrict__ b2,
                                                    const float* __restrict__ res,
                                                    float* __restrict__ out)
{
    extern __shared__ char smem[];
    const uint32_t sb = smem_u32(smem);

    const int tid  = threadIdx.x;
    const int wid  = tid >> 5, lane = tid & 31;
    const int wm   = wid & 1,  wn   = wid >> 1;
    const int g    = lane >> 2, t4  = lane & 3;
    const int lg   = lane >> 3, lr  = lane & 7;
    const long m0  = (long)blockIdx.x * 64;

    uint32_t pA[2], xA[2];
#pragma unroll
    for (int mi = 0; mi < 2; mi++) {
        int row = wm * 32 + mi * 16 + (lg & 1) * 8 + lr;
        pA[mi] = (uint32_t)row * 128;
        xA[mi] = (uint32_t)(row & 7) * 16;
    }
    const uint32_t hiA = (uint32_t)(lg >> 1) * 16;
    uint32_t pB[3], xB[3];
#pragma unroll
    for (int p = 0; p < 3; p++) {
        int row = wn * 48 + p * 16 + ((lg >> 1) & 1) * 8 + lr;
        pB[p] = (uint32_t)row * 128;
        xB[p] = (uint32_t)(row & 7) * 16;
    }
    const uint32_t hiB = (uint32_t)(lg & 1) * 16;

    auto load_tile = [&](int idx) {
        const int hc = idx / 6, j = idx % 6;
        const uint32_t dst = sb + MF_RING + (uint32_t)(idx & 1) * 24576;
#pragma unroll
        for (int i = 0; i < 6; i++) {
            int q = tid + i * 256;
            int row = q >> 3, ch = q & 7;
            const __half* src;
            if (j < 3)
                src = W1T + (size_t)(hc * 192 + row) * CDIM + j * 64 + ch * 8;
            else
                src = W2T + (size_t)row * HID + hc * 192 + (j - 3) * 64 + ch * 8;
            cp16s(dst + (uint32_t)row * 128 + (uint32_t)((ch ^ (row & 7)) * 16), src);
        }
    };

#pragma unroll
    for (int t = 0; t < 3; t++)
#pragma unroll
        for (int i = 0; i < 2; i++) {
            int q = tid + i * 256;
            int row = q >> 3, ch = q & 7;
            cp16s(sb + MF_A + (uint32_t)t * 8192 + (uint32_t)row * 128 +
                      (uint32_t)((ch ^ (row & 7)) * 16),
                  A + (m0 + row) * (size_t)CDIM + t * 64 + ch * 8);
        }
    load_tile(0);
    asm volatile("cp.async.commit_group;");
    load_tile(1);
    asm volatile("cp.async.commit_group;");

    float accO[2][6][4];
#pragma unroll
    for (int mi = 0; mi < 2; mi++)
#pragma unroll
        for (int nj = 0; nj < 6; nj++)
#pragma unroll
            for (int r = 0; r < 4; r++) accO[mi][nj][r] = 0.f;

    float accH[2][6][4];

    for (int idx = 0; idx < 24; idx++) {
        if (idx < 23) { asm volatile("cp.async.wait_group 1;"); }
        else          { asm volatile("cp.async.wait_group 0;"); }
        __syncthreads();

        const int hc = idx / 6, j = idx % 6;
        const bool ph1 = (j < 3);
        const int sub  = ph1 ? j : j - 3;
        const uint32_t sa  = ph1 ? (sb + MF_A + (uint32_t)sub * 8192)
                                 : (sb + MF_H + (uint32_t)sub * 8192);
        const uint32_t sbB = sb + MF_RING + (uint32_t)(idx & 1) * 24576;

        if (ph1 && sub == 0) {
#pragma unroll
            for (int mi = 0; mi < 2; mi++)
#pragma unroll
                for (int nj = 0; nj < 6; nj++)
#pragma unroll
                    for (int r = 0; r < 4; r++) accH[mi][nj][r] = 0.f;
        }

#pragma unroll
        for (int s = 0; s < 4; s++) {
            const uint32_t cs = (uint32_t)(s * 32);
            uint32_t a[2][4], b[6][2];
#pragma unroll
            for (int mi = 0; mi < 2; mi++)
                ldsm4(a[mi], sa + pA[mi] + ((cs + hiA) ^ xA[mi]));
#pragma unroll
            for (int p = 0; p < 3; p++) {
                uint32_t r[4];
                ldsm4(r, sbB + pB[p] + ((cs + hiB) ^ xB[p]));
                b[2 * p][0]     = r[0]; b[2 * p][1]     = r[1];
                b[2 * p + 1][0] = r[2]; b[2 * p + 1][1] = r[3];
            }
            if (ph1) {
#pragma unroll
                for (int mi = 0; mi < 2; mi++)
#pragma unroll
                    for (int nj = 0; nj < 6; nj++)
                        mma_f16(accH[mi][nj], a[mi], b[nj]);
            } else {
#pragma unroll
                for (int mi = 0; mi < 2; mi++)
#pragma unroll
                    for (int nj = 0; nj < 6; nj++)
                        mma_f16(accO[mi][nj], a[mi], b[nj]);
            }
        }
        __syncthreads();

        if (ph1 && sub == 2) {
#pragma unroll
            for (int mi = 0; mi < 2; mi++) {
#pragma unroll
                for (int hh = 0; hh < 2; hh++) {
                    int r = wm * 32 + mi * 16 + g + hh * 8;
#pragma unroll
                    for (int nj = 0; nj < 6; nj++) {
                        int cb = wn * 48 + nj * 8 + 2 * t4;
                        int hcol = hc * 192 + cb;
                        float o0 = accH[mi][nj][hh * 2 + 0] + __ldg(b1 + hcol);
                        float o1 = accH[mi][nj][hh * 2 + 1] + __ldg(b1 + hcol + 1);
                        o0 = 0.5f * o0 * (1.0f + erff(o0 * 0.7071067811865476f));
                        o1 = 0.5f * o1 * (1.0f + erff(o1 * 0.7071067811865476f));
                        __half2 hv2 = __floats2half2_rn(o0, o1);
                        uint32_t hv = *(uint32_t*)&hv2;
                        uint32_t haddr = sb + MF_H + (uint32_t)((cb >> 6) << 13) +
                                         (uint32_t)r * 128 +
                                         (uint32_t)(((((cb & 63) >> 3) ^ (r & 7)) << 4) +
                                                    ((cb & 7) << 1));
                        asm volatile("st.shared.b32 [%0], %1;" :: "r"(haddr), "r"(hv));
                    }
                }
            }
            __syncthreads();
        }

        if (idx + 2 < 24) {
            load_tile(idx + 2);
            asm volatile("cp.async.commit_group;");
        }
    }

#pragma unroll
    for (int mi = 0; mi < 2; mi++) {
#pragma unroll
        for (int hh = 0; hh < 2; hh++) {
            long r = m0 + wm * 32 + mi * 16 + g + hh * 8;
#pragma unroll
            for (int nj = 0; nj < 6; nj++) {
                int cb = wn * 48 + nj * 8 + 2 * t4;
                float o0 = accO[mi][nj][hh * 2 + 0] + __ldg(b2 + cb);
                float o1 = accO[mi][nj][hh * 2 + 1] + __ldg(b2 + cb + 1);
                const float2 rv = *(const float2*)(res + r * (size_t)CDIM + cb);
                o0 += rv.x; o1 += rv.y;
                *(float2*)(out + r * (size_t)CDIM + cb) = make_float2(o0, o1);
            }
        }
    }
}

// ---------------- Windowed attention via fp16 tensor cores ----------------
#define AP 40
#define SP 65
#define PP 72

__global__ void __launch_bounds__(128) attn_kernel(const float* __restrict__ attn_bias)
{
    __shared__ __half qs[64 * AP];
    __shared__ __half ks[64 * AP];
    __shared__ __half vs[64 * AP];
    __shared__ float  S [64 * SP];
    __shared__ __half P [64 * PP];
    __shared__ float  bh[49];
    __shared__ int    grow[49];

    const int tid = threadIdx.x;
    const int w   = tid >> 5, lane = tid & 31;
    const int g   = lane >> 2, t4 = lane & 3;
    const int lg  = lane >> 3, lr = lane & 7;
    const int wid = blockIdx.x;
    const int h   = blockIdx.y;
    const int b   = wid >> 6;
    const int wr  = wid & 63;
    const int wy  = wr >> 3, wx = wr & 7;

    const uint32_t qsb = smem_u32(qs), ksb = smem_u32(ks), vsb = smem_u32(vs);
    const uint32_t Pb  = smem_u32(P);

    if (tid < 49) {
        int ty = tid / 7, tx = tid - ty * 7;
        grow[tid] = b * 3136 + (wy * 7 + ty) * HW + (wx * 7 + tx);
        bh[tid]   = attn_bias[h * 49 + tid];
    }
    {
        uint32_t* z0 = (uint32_t*)qs;
        uint32_t* z1 = (uint32_t*)ks;
        uint32_t* z2 = (uint32_t*)vs;
        for (int i = tid; i < 64 * AP / 2; i += 128) { z0[i] = 0; z1[i] = 0; z2[i] = 0; }
        uint32_t* z3 = (uint32_t*)P;
        for (int i = tid; i < 64 * PP / 2; i += 128) z3[i] = 0;
    }
    __syncthreads();

    for (int i = tid; i < 588; i += 128) {
        int t = i / 12;
        int rm = i - t * 12;
        int tensor = rm >> 2, ch = rm & 3;
        const __half* src = g_qkv + (size_t)grow[t] * QKVN + h * 96 + tensor * 32 + ch * 8;
        uint32_t base = (tensor == 0) ? qsb : (tensor == 1) ? ksb : vsb;
        cp16s(base + (uint32_t)t * 80 + (uint32_t)ch * 16, src);
    }
    asm volatile("cp.async.commit_group;");
    asm volatile("cp.async.wait_group 0;");
    __syncthreads();

    float acc[8][4];
#pragma unroll
    for (int nj = 0; nj < 8; nj++)
#pragma unroll
        for (int r = 0; r < 4; r++) acc[nj][r] = 0.f;

    const uint32_t aaddr = qsb + (uint32_t)(w * 16 + (lg & 1) * 8 + lr) * 80 + (uint32_t)(lg >> 1) * 16;
    const uint32_t baddr = ksb + (uint32_t)(((lg >> 1) & 1) * 8 + lr) * 80 + (uint32_t)(lg & 1) * 16;
#pragma unroll
    for (int s = 0; s < 2; s++) {
        uint32_t a[4];
        ldsm4(a, aaddr + s * 32);
#pragma unroll
        for (int p = 0; p < 4; p++) {
            uint32_t r[4];
            ldsm4(r, baddr + (uint32_t)p * (16 * 80) + s * 32);
            uint32_t b0[2] = {r[0], r[1]}, b1[2] = {r[2], r[3]};
            mma_f16(acc[2 * p], a, b0);
            mma_f16(acc[2 * p + 1], a, b1);
        }
    }

    const float scale = 0.17677669529663687f;
#pragma unroll
    for (int nj = 0; nj < 8; nj++) {
#pragma unroll
        for (int hh = 0; hh < 2; hh++) {
            int rr = w * 16 + g + hh * 8;
            int rn = rr / 7, cn = rr - rn * 7;
#pragma unroll
            for (int q = 0; q < 2; q++) {
                int cc = nj * 8 + 2 * t4 + q;
                float v = acc[nj][hh * 2 + q] * scale;
                if (rr < 49 && cc < 49) {
                    int rm2 = cc / 7, cm2 = cc - rm2 * 7;
                    v += bh[abs(rn - rm2) * 7 + abs(cn - cm2)];
                }
                S[rr * SP + cc] = v;
            }
        }
    }
    __syncthreads();

    if (tid < 49) {
        float mx = -1e30f;
        for (int m = 0; m < 49; m++) mx = fmaxf(mx, S[tid * SP + m]);
        float sum = 0.f;
        float e[49];
#pragma unroll 7
        for (int m = 0; m < 49; m++) {
            e[m] = __expf(S[tid * SP + m] - mx);
            sum += e[m];
        }
        float inv = 1.0f / sum;
        for (int m = 0; m < 49; m++)
            P[tid * PP + m] = __float2half(e[m] * inv);
    }
    __syncthreads();

    float acc2[4][4];
#pragma unroll
    for (int nj = 0; nj < 4; nj++)
#pragma unroll
        for (int r = 0; r < 4; r++) acc2[nj][r] = 0.f;

    const uint32_t paddr = Pb + (uint32_t)(w * 16 + (lg & 1) * 8 + lr) * 144 + (uint32_t)(lg >> 1) * 16;
    const uint32_t vaddr = vsb + (uint32_t)((lg & 1) * 8 + lr) * 80 + (uint32_t)(lg >> 1) * 16;
#pragma unroll
    for (int s = 0; s < 4; s++) {
        uint32_t a[4];
        ldsm4(a, paddr + s * 32);
        uint32_t r0[4], r1[4];
        ldsm4t(r0, vaddr + (uint32_t)s * (16 * 80));
        ldsm4t(r1, vaddr + (uint32_t)s * (16 * 80) + 32);
        uint32_t b0[2] = {r0[0], r0[1]}, b1[2] = {r0[2], r0[3]};
        uint32_t b2[2] = {r1[0], r1[1]}, b3[2] = {r1[2], r1[3]};
        mma_f16(acc2[0], a, b0);
        mma_f16(acc2[1], a, b1);
        mma_f16(acc2[2], a, b2);
        mma_f16(acc2[3], a, b3);
    }

#pragma unroll
    for (int hh = 0; hh < 2; hh++) {
        int rr = w * 16 + g + hh * 8;
        if (rr < 49) {
            __half* orow = g_attn + (size_t)grow[rr] * CDIM + h * KD;
#pragma unroll
            for (int nj = 0; nj < 4; nj++) {
                int d = nj * 8 + 2 * t4;
                *(__half2*)(orow + d) =
                    __floats2half2_rn(acc2[nj][hh * 2 + 0], acc2[nj][hh * 2 + 1]);
            }
        }
    }
}

// ---------------- fused depthwise 3x3 conv + BN + LN2, 4 pixels/block ----------------
__global__ void __launch_bounds__(192) dwconv_bn_ln_kernel(const float* __restrict__ w,
                                                           const float* __restrict__ bg,
                                                           const float* __restrict__ bb,
                                                           const float* __restrict__ bmean,
                                                           const float* __restrict__ bvar,
                                                           const float* __restrict__ g2,
                                                           const float* __restrict__ b2)
{
    __shared__ float red[6][4];
    const int bid = blockIdx.x;
    const int cg  = bid % 14;
    const int tmp = bid / 14;
    const int r   = tmp % HW;
    const int bbi = tmp / HW;
    const int c0  = cg * 4;
    const int ch  = threadIdx.x;
    const int wd  = ch >> 5, lane = ch & 31;

    float w9[9];
#pragma unroll
    for (int i = 0; i < 9; i++) w9[i] = w[ch * 9 + i];

    float acc[4] = {0.f, 0.f, 0.f, 0.f};
#pragma unroll
    for (int kh = 0; kh < 3; kh++) {
        int rr = r + kh - 1;
        if (rr < 0 || rr >= HW) continue;
        const float* rowb = g_x1 + ((size_t)bbi * 3136 + rr * HW) * CDIM + ch;
        float vals[6];
#pragma unroll
        for (int j = 0; j < 6; j++) {
            int col = c0 - 1 + j;
            vals[j] = (col >= 0 && col < HW) ? rowb[col * CDIM] : 0.f;
        }
#pragma unroll
        for (int p = 0; p < 4; p++)
#pragma unroll
            for (int kw = 0; kw < 3; kw++)
                acc[p] += vals[p + kw] * w9[kh * 3 + kw];
    }

    const float inv = rsqrtf(bvar[ch] + 1e-5f);
    const float sc  = bg[ch] * inv;
    const float mu  = bmean[ch];
    const float bt  = bb[ch];
    float bnv[4];
#pragma unroll
    for (int p = 0; p < 4; p++) {
        bnv[p] = (acc[p] - mu) * sc + bt;
        g_x2[((size_t)bbi * 3136 + r * HW + c0 + p) * CDIM + ch] = bnv[p];
    }

    float s0 = bnv[0], s1 = bnv[1], s2 = bnv[2], s3 = bnv[3];
#pragma unroll
    for (int o = 16; o > 0; o >>= 1) {
        s0 += __shfl_xor_sync(0xffffffffu, s0, o);
        s1 += __shfl_xor_sync(0xffffffffu, s1, o);
        s2 += __shfl_xor_sync(0xffffffffu, s2, o);
        s3 += __shfl_xor_sync(0xffffffffu, s3, o);
    }
    if (lane == 0) { red[wd][0] = s0; red[wd][1] = s1; red[wd][2] = s2; red[wd][3] = s3; }
    __syncthreads();
    float mean[4];
#pragma unroll
    for (int p = 0; p < 4; p++)
        mean[p] = (red[0][p] + red[1][p] + red[2][p] + red[3][p] + red[4][p] + red[5][p]) * (1.0f / 192.0f);
    __syncthreads();

    float d[4];
    float q0, q1, q2, q3;
    d[0] = bnv[0] - mean[0]; q0 = d[0] * d[0];
    d[1] = bnv[1] - mean[1]; q1 = d[1] * d[1];
    d[2] = bnv[2] - mean[2]; q2 = d[2] * d[2];
    d[3] = bnv[3] - mean[3]; q3 = d[3] * d[3];
#pragma unroll
    for (int o = 16; o > 0; o >>= 1) {
        q0 += __shfl_xor_sync(0xffffffffu, q0, o);
        q1 += __shfl_xor_sync(0xffffffffu, q1, o);
        q2 += __shfl_xor_sync(0xffffffffu, q2, o);
        q3 += __shfl_xor_sync(0xffffffffu, q3, o);
    }
    if (lane == 0) { red[wd][0] = q0; red[wd][1] = q1; red[wd][2] = q2; red[wd][3] = q3; }
    __syncthreads();

    const float gg = g2[ch], b2v = b2[ch];
#pragma unroll
    for (int p = 0; p < 4; p++) {
        float var = (red[0][p] + red[1][p] + red[2][p] + red[3][p] + red[4][p] + red[5][p]) * (1.0f / 192.0f);
        float rstd = rsqrtf(var + 1e-5f);
        g_ln[((size_t)bbi * 3136 + r * HW + c0 + p) * CDIM + ch] =
            __float2half(d[p] * rstd * gg + b2v);
    }
}

// ---------------- launch ----------------
extern "C" void kernel_launch(void* const* d_in, const int* in_sizes, int n_in,
                              void* d_out, int out_size)
{
    (void)in_sizes; (void)n_in; (void)out_size;
    const float* x        = (const float*)d_in[0];
    const float* norm1_g  = (const float*)d_in[1];
    const float* norm1_b  = (const float*)d_in[2];
    const float* qkv_w    = (const float*)d_in[3];
    const float* qkv_b    = (const float*)d_in[4];
    const float* attnbias = (const float*)d_in[5];
    const float* proj_w   = (const float*)d_in[6];
    const float* proj_b   = (const float*)d_in[7];
    const float* conv_w   = (const float*)d_in[8];
    const float* bn_g     = (const float*)d_in[9];
    const float* bn_b     = (const float*)d_in[10];
    const float* bn_mean  = (const float*)d_in[11];
    const float* bn_var   = (const float*)d_in[12];
    const float* norm2_g  = (const float*)d_in[13];
    const float* norm2_b  = (const float*)d_in[14];
    const float* fc1_w    = (const float*)d_in[15];
    const float* fc1_b    = (const float*)d_in[16];
    const float* fc2_w    = (const float*)d_in[17];
    const float* fc2_b    = (const float*)d_in[18];
    float* out = (float*)d_out;

    __half *p_ln, *p_qkv, *p_attn, *p_wt;
    float  *p_x1, *p_x2;
    cudaGetSymbolAddress((void**)&p_ln,   g_ln);
    cudaGetSymbolAddress((void**)&p_qkv,  g_qkv);
    cudaGetSymbolAddress((void**)&p_attn, g_attn);
    cudaGetSymbolAddress((void**)&p_x1,   g_x1);
    cudaGetSymbolAddress((void**)&p_x2,   g_x2);
    cudaGetSymbolAddress((void**)&p_wt,   g_wt);

    cudaFuncSetAttribute(qkv_ln_gemm, cudaFuncAttributeMaxDynamicSharedMemorySize, QL_SMEM);
    cudaFuncSetAttribute(gemm_h<2>,   cudaFuncAttributeMaxDynamicSharedMemorySize, GT_SMEM);
    cudaFuncSetAttribute(mlp_fused,   cudaFuncAttributeMaxDynamicSharedMemorySize, MF_SMEM);

    // 1) all weight transposes in one launch
    transpose_all<<<432, 256>>>(qkv_w, proj_w, fc1_w, fc2_w, p_wt);
    // 2) fused LN1 + QKV GEMM
    qkv_ln_gemm<<<dim3(MROWS / 64, 3), 256, QL_SMEM>>>(x, p_wt + W_QKV, qkv_b,
                                                       norm1_g, norm1_b, p_qkv);
    // 3) windowed attention
    attn_kernel<<<dim3(2048, NHEADS), 128>>>(attnbias);
    // 4) proj GEMM + residual x -> g_x1 (f32)   [ncu sample lands here]
    gemm_h<2><<<dim3(MROWS / 64, 1), 256, GT_SMEM>>>(p_attn, p_wt + W_PROJ, proj_b, x, p_x1, CDIM, CDIM);
    // 5) depthwise conv + BN + LN2 (fused, 4 px/block)
    dwconv_bn_ln_kernel<<<32 * HW * (HW / 4), CDIM>>>(conv_w, bn_g, bn_b, bn_mean, bn_var, norm2_g, norm2_b);
    // 6) fused MLP: out = x2 + fc2(gelu(fc1(ln2)))
    mlp_fused<<<MROWS / 64, 256, MF_SMEM>>>(p_ln, p_wt + W_FC1, p_wt + W_FC2,
                                            fc1_b, fc2_b, p_x2, out);
}

// round 13
// speedup vs baseline: 1.0634x; 1.0634x over previous
#include <cuda_runtime.h>
#include <cuda_fp16.h>
#include <math.h>
#include <stdint.h>

// ---------------- constants ----------------
#define MROWS  100352      // 32 * 3136
#define CDIM   192
#define NHEADS 6
#define KD     32
#define QKVN   576
#define HID    768
#define HW     56

// transposed fp16 weight scratch offsets (all [N,K] K-major)
#define W_QKV  0
#define W_PROJ 110592
#define W_FC1  147456
#define W_FC2  294912
#define W_TOT  442368

// ---------------- scratch ----------------
__device__ __half g_ln  [(size_t)MROWS * CDIM];
__device__ __half g_qkv [(size_t)MROWS * QKVN];
__device__ __half g_attn[(size_t)MROWS * CDIM];
__device__ __half g_mlp [(size_t)MROWS * HID];
__device__ __half g_x1  [(size_t)MROWS * CDIM];   // fp16 residual stream (R13)
__device__ float  g_x2  [(size_t)MROWS * CDIM];
__device__ __half g_wt  [W_TOT];

// ---------------- helpers ----------------
__device__ __forceinline__ uint32_t smem_u32(const void* p) {
    uint32_t a;
    asm("{ .reg .u64 t; cvta.to.shared.u64 t, %1; cvt.u32.u64 %0, t; }" : "=r"(a) : "l"(p));
    return a;
}

__device__ __forceinline__ void cp16s(uint32_t s, const void* g) {
    asm volatile("cp.async.ca.shared.global [%0], [%1], 16;" :: "r"(s), "l"(g));
}

__device__ __forceinline__ void ldsm4(uint32_t* r, uint32_t addr) {
    asm volatile("ldmatrix.sync.aligned.m8n8.x4.shared.b16 {%0,%1,%2,%3}, [%4];"
                 : "=r"(r[0]), "=r"(r[1]), "=r"(r[2]), "=r"(r[3]) : "r"(addr));
}

__device__ __forceinline__ void ldsm4t(uint32_t* r, uint32_t addr) {
    asm volatile("ldmatrix.sync.aligned.m8n8.x4.trans.shared.b16 {%0,%1,%2,%3}, [%4];"
                 : "=r"(r[0]), "=r"(r[1]), "=r"(r[2]), "=r"(r[3]) : "r"(addr));
}

__device__ __forceinline__ void mma_f16(float* d, const uint32_t* a, const uint32_t* b) {
    asm volatile(
        "mma.sync.aligned.m16n8k16.row.col.f32.f16.f16.f32 "
        "{%0,%1,%2,%3}, {%4,%5,%6,%7}, {%8,%9}, {%0,%1,%2,%3};"
        : "+f"(d[0]), "+f"(d[1]), "+f"(d[2]), "+f"(d[3])
        : "r"(a[0]), "r"(a[1]), "r"(a[2]), "r"(a[3]), "r"(b[0]), "r"(b[1]));
}

// ---------------- merged weight transpose: 4 tensors in one launch ----------------
__global__ void __launch_bounds__(256) transpose_all(const float* __restrict__ qkv_w,
                                                     const float* __restrict__ proj_w,
                                                     const float* __restrict__ fc1_w,
                                                     const float* __restrict__ fc2_w,
                                                     __half* __restrict__ wt)
{
    __shared__ float t[32][33];
    int bid = blockIdx.x;
    const float* src; __half* dst; int Kdim, Ndim, bx, by;
    if (bid < 108)      { src = qkv_w;  dst = wt + W_QKV;  Kdim = CDIM; Ndim = QKVN; int q = bid;       bx = q % 18; by = q / 18; }
    else if (bid < 144) { src = proj_w; dst = wt + W_PROJ; Kdim = CDIM; Ndim = CDIM; int q = bid - 108; bx = q % 6;  by = q / 6; }
    else if (bid < 288) { src = fc1_w;  dst = wt + W_FC1;  Kdim = CDIM; Ndim = HID;  int q = bid - 144; bx = q % 24; by = q / 24; }
    else                { src = fc2_w;  dst = wt + W_FC2;  Kdim = HID;  Ndim = CDIM; int q = bid - 288; bx = q % 6;  by = q / 6; }

    int n0 = bx * 32, k0 = by * 32;
    int tx = threadIdx.x & 31, ty = threadIdx.x >> 5;
#pragma unroll
    for (int i = ty; i < 32; i += 8)
        t[i][tx] = src[(size_t)(k0 + i) * Ndim + n0 + tx];
    __syncthreads();
#pragma unroll
    for (int i = ty; i < 32; i += 8)
        dst[(size_t)(n0 + i) * Kdim + k0 + tx] = __float2half(t[tx][i]);
}

// ---------------- LayerNorm (LN1): fp16 output ----------------
__global__ void __launch_bounds__(256) ln_kernel(const float* __restrict__ x,
                                                 const float* __restrict__ g,
                                                 const float* __restrict__ b,
                                                 __half* __restrict__ out)
{
    int warp = threadIdx.x >> 5;
    int lane = threadIdx.x & 31;
    long row = (long)blockIdx.x * 8 + warp;
    const float* xr = x + row * CDIM;

    float v[6];
#pragma unroll
    for (int i = 0; i < 6; i++) v[i] = xr[lane + 32 * i];

    float s = 0.f;
#pragma unroll
    for (int i = 0; i < 6; i++) s += v[i];
#pragma unroll
    for (int o = 16; o > 0; o >>= 1) s += __shfl_xor_sync(0xffffffffu, s, o);
    float mean = s * (1.0f / 192.0f);

    float sq = 0.f;
#pragma unroll
    for (int i = 0; i < 6; i++) { float d = v[i] - mean; sq += d * d; }
#pragma unroll
    for (int o = 16; o > 0; o >>= 1) sq += __shfl_xor_sync(0xffffffffu, sq, o);
    float rstd = rsqrtf(sq * (1.0f / 192.0f) + 1e-5f);

    __half* orow = out + row * CDIM;
#pragma unroll
    for (int i = 0; i < 6; i++) {
        int c = lane + 32 * i;
        orow[c] = __float2half((v[i] - mean) * rstd * g[c] + b[c]);
    }
}

// ---------------- FP16 mma GEMM: BM=64, BN=192, BK=64, 3-stage, 2 CTAs/SM ----------------
// EPI: 0 bias->fp16 | 1 bias+GELU->fp16 | 2 bias+res(f32)->f32 | 3 bias+res(f32)->fp16
#define GT_BOFF  8192
#define GT_STAGE 32768
#define GT_SMEM  (3 * GT_STAGE)

template <int EPI>
__global__ void __launch_bounds__(256, 2) gemm_h(const __half* __restrict__ A,
                                                 const __half* __restrict__ BT,
                                                 const float* __restrict__ bias,
                                                 const float* __restrict__ res,
                                                 void* __restrict__ Cout,
                                                 int N, int K)
{
    extern __shared__ char smem[];
    const uint32_t sb = smem_u32(smem);

    const int tid  = threadIdx.x;
    const int wid  = tid >> 5, lane = tid & 31;
    const int wm   = wid & 1,  wn   = wid >> 1;
    const int g    = lane >> 2, t4  = lane & 3;
    const int lg   = lane >> 3, lr  = lane & 7;
    const long m0  = (long)blockIdx.x * 64;
    const int  n0  = blockIdx.y * 192;
    const int  T   = K >> 6;

    float acc[2][6][4];
#pragma unroll
    for (int mi = 0; mi < 2; mi++)
#pragma unroll
        for (int nj = 0; nj < 6; nj++)
#pragma unroll
            for (int r = 0; r < 4; r++) acc[mi][nj][r] = 0.f;

    uint32_t pA[2], xA[2];
#pragma unroll
    for (int mi = 0; mi < 2; mi++) {
        int row = wm * 32 + mi * 16 + (lg & 1) * 8 + lr;
        pA[mi] = (uint32_t)row * 128;
        xA[mi] = (uint32_t)(row & 7) * 16;
    }
    const uint32_t hiA = (uint32_t)(lg >> 1) * 16;
    uint32_t pB[3], xB[3];
#pragma unroll
    for (int p = 0; p < 3; p++) {
        int row = wn * 48 + p * 16 + ((lg >> 1) & 1) * 8 + lr;
        pB[p] = (uint32_t)row * 128;
        xB[p] = (uint32_t)(row & 7) * 16;
    }
    const uint32_t hiB = (uint32_t)(lg & 1) * 16;

    auto load_stage = [&](int t, int st) {
        const uint32_t sa = sb + (uint32_t)st * GT_STAGE;
        const int kf = t << 6;
#pragma unroll
        for (int i = 0; i < 2; i++) {
            int q = tid + i * 256;
            int row = q >> 3, ch = q & 7;
            cp16s(sa + (uint32_t)row * 128 + (uint32_t)((ch ^ (row & 7)) * 16),
                  A + (m0 + row) * (size_t)K + kf + ch * 8);
        }
#pragma unroll
        for (int i = 0; i < 6; i++) {
            int q = tid + i * 256;
            int row = q >> 3, ch = q & 7;
            cp16s(sa + GT_BOFF + (uint32_t)row * 128 + (uint32_t)((ch ^ (row & 7)) * 16),
                  BT + (size_t)(n0 + row) * K + kf + ch * 8);
        }
    };

    load_stage(0, 0);
    asm volatile("cp.async.commit_group;");
    load_stage(1, 1);
    asm volatile("cp.async.commit_group;");

    for (int t = 0; t < T; t++) {
        if (t + 2 < T) load_stage(t + 2, (t + 2) % 3);
        asm volatile("cp.async.commit_group;");
        asm volatile("cp.async.wait_group 2;");
        __syncthreads();

        const uint32_t sa  = sb + (uint32_t)(t % 3) * GT_STAGE;
        const uint32_t sbB = sa + GT_BOFF;
#pragma unroll
        for (int s = 0; s < 4; s++) {
            const uint32_t cs = (uint32_t)(s * 32);
            uint32_t a[2][4], b[6][2];
#pragma unroll
            for (int mi = 0; mi < 2; mi++)
                ldsm4(a[mi], sa + pA[mi] + ((cs + hiA) ^ xA[mi]));
#pragma unroll
            for (int p = 0; p < 3; p++) {
                uint32_t r[4];
                ldsm4(r, sbB + pB[p] + ((cs + hiB) ^ xB[p]));
                b[2 * p][0]     = r[0]; b[2 * p][1]     = r[1];
                b[2 * p + 1][0] = r[2]; b[2 * p + 1][1] = r[3];
            }
#pragma unroll
            for (int mi = 0; mi < 2; mi++)
#pragma unroll
                for (int nj = 0; nj < 6; nj++)
                    mma_f16(acc[mi][nj], a[mi], b[nj]);
        }
        __syncthreads();
    }

#pragma unroll
    for (int mi = 0; mi < 2; mi++) {
#pragma unroll
        for (int half = 0; half < 2; half++) {
            long r = m0 + wm * 32 + mi * 16 + g + half * 8;
#pragma unroll
            for (int nj = 0; nj < 6; nj++) {
                int cb = n0 + wn * 48 + nj * 8 + 2 * t4;
                float o0 = acc[mi][nj][half * 2 + 0] + __ldg(bias + cb);
                float o1 = acc[mi][nj][half * 2 + 1] + __ldg(bias + cb + 1);
                if (EPI == 1) {
                    o0 = 0.5f * o0 * (1.0f + erff(o0 * 0.7071067811865476f));
                    o1 = 0.5f * o1 * (1.0f + erff(o1 * 0.7071067811865476f));
                }
                if (EPI == 2 || EPI == 3) {
                    const float2 rv = *(const float2*)(res + r * (size_t)N + cb);
                    o0 += rv.x; o1 += rv.y;
                }
                if (EPI == 2) {
                    *(float2*)((float*)Cout + r * (size_t)N + cb) = make_float2(o0, o1);
                } else {
                    __half2 hv = __floats2half2_rn(o0, o1);
                    *(__half2*)((__half*)Cout + r * (size_t)N + cb) = hv;
                }
            }
        }
    }
}

// ---------------- Windowed attention via fp16 tensor cores ----------------
#define AP 40
#define SP 65
#define PP 72

__global__ void __launch_bounds__(128) attn_kernel(const float* __restrict__ attn_bias)
{
    __shared__ __half qs[64 * AP];
    __shared__ __half ks[64 * AP];
    __shared__ __half vs[64 * AP];
    __shared__ float  S [64 * SP];
    __shared__ __half P [64 * PP];
    __shared__ float  bh[49];
    __shared__ int    grow[49];

    const int tid = threadIdx.x;
    const int w   = tid >> 5, lane = tid & 31;
    const int g   = lane >> 2, t4 = lane & 3;
    const int lg  = lane >> 3, lr = lane & 7;
    const int wid = blockIdx.x;
    const int h   = blockIdx.y;
    const int b   = wid >> 6;
    const int wr  = wid & 63;
    const int wy  = wr >> 3, wx = wr & 7;

    const uint32_t qsb = smem_u32(qs), ksb = smem_u32(ks), vsb = smem_u32(vs);
    const uint32_t Pb  = smem_u32(P);

    if (tid < 49) {
        int ty = tid / 7, tx = tid - ty * 7;
        grow[tid] = b * 3136 + (wy * 7 + ty) * HW + (wx * 7 + tx);
        bh[tid]   = attn_bias[h * 49 + tid];
    }
    {
        uint32_t* z0 = (uint32_t*)qs;
        uint32_t* z1 = (uint32_t*)ks;
        uint32_t* z2 = (uint32_t*)vs;
        for (int i = tid; i < 64 * AP / 2; i += 128) { z0[i] = 0; z1[i] = 0; z2[i] = 0; }
        uint32_t* z3 = (uint32_t*)P;
        for (int i = tid; i < 64 * PP / 2; i += 128) z3[i] = 0;
    }
    __syncthreads();

    for (int i = tid; i < 588; i += 128) {
        int t = i / 12;
        int rm = i - t * 12;
        int tensor = rm >> 2, ch = rm & 3;
        const __half* src = g_qkv + (size_t)grow[t] * QKVN + h * 96 + tensor * 32 + ch * 8;
        uint32_t base = (tensor == 0) ? qsb : (tensor == 1) ? ksb : vsb;
        cp16s(base + (uint32_t)t * 80 + (uint32_t)ch * 16, src);
    }
    asm volatile("cp.async.commit_group;");
    asm volatile("cp.async.wait_group 0;");
    __syncthreads();

    float acc[8][4];
#pragma unroll
    for (int nj = 0; nj < 8; nj++)
#pragma unroll
        for (int r = 0; r < 4; r++) acc[nj][r] = 0.f;

    const uint32_t aaddr = qsb + (uint32_t)(w * 16 + (lg & 1) * 8 + lr) * 80 + (uint32_t)(lg >> 1) * 16;
    const uint32_t baddr = ksb + (uint32_t)(((lg >> 1) & 1) * 8 + lr) * 80 + (uint32_t)(lg & 1) * 16;
#pragma unroll
    for (int s = 0; s < 2; s++) {
        uint32_t a[4];
        ldsm4(a, aaddr + s * 32);
#pragma unroll
        for (int p = 0; p < 4; p++) {
            uint32_t r[4];
            ldsm4(r, baddr + (uint32_t)p * (16 * 80) + s * 32);
            uint32_t b0[2] = {r[0], r[1]}, b1[2] = {r[2], r[3]};
            mma_f16(acc[2 * p], a, b0);
            mma_f16(acc[2 * p + 1], a, b1);
        }
    }

    const float scale = 0.17677669529663687f;
#pragma unroll
    for (int nj = 0; nj < 8; nj++) {
#pragma unroll
        for (int hh = 0; hh < 2; hh++) {
            int rr = w * 16 + g + hh * 8;
            int rn = rr / 7, cn = rr - rn * 7;
#pragma unroll
            for (int q = 0; q < 2; q++) {
                int cc = nj * 8 + 2 * t4 + q;
                float v = acc[nj][hh * 2 + q] * scale;
                if (rr < 49 && cc < 49) {
                    int rm2 = cc / 7, cm2 = cc - rm2 * 7;
                    v += bh[abs(rn - rm2) * 7 + abs(cn - cm2)];
                }
                S[rr * SP + cc] = v;
            }
        }
    }
    __syncthreads();

    if (tid < 49) {
        float mx = -1e30f;
        for (int m = 0; m < 49; m++) mx = fmaxf(mx, S[tid * SP + m]);
        float sum = 0.f;
        float e[49];
#pragma unroll 7
        for (int m = 0; m < 49; m++) {
            e[m] = __expf(S[tid * SP + m] - mx);
            sum += e[m];
        }
        float inv = 1.0f / sum;
        for (int m = 0; m < 49; m++)
            P[tid * PP + m] = __float2half(e[m] * inv);
    }
    __syncthreads();

    float acc2[4][4];
#pragma unroll
    for (int nj = 0; nj < 4; nj++)
#pragma unroll
        for (int r = 0; r < 4; r++) acc2[nj][r] = 0.f;

    const uint32_t paddr = Pb + (uint32_t)(w * 16 + (lg & 1) * 8 + lr) * 144 + (uint32_t)(lg >> 1) * 16;
    const uint32_t vaddr = vsb + (uint32_t)((lg & 1) * 8 + lr) * 80 + (uint32_t)(lg >> 1) * 16;
#pragma unroll
    for (int s = 0; s < 4; s++) {
        uint32_t a[4];
        ldsm4(a, paddr + s * 32);
        uint32_t r0[4], r1[4];
        ldsm4t(r0, vaddr + (uint32_t)s * (16 * 80));
        ldsm4t(r1, vaddr + (uint32_t)s * (16 * 80) + 32);
        uint32_t b0[2] = {r0[0], r0[1]}, b1[2] = {r0[2], r0[3]};
        uint32_t b2[2] = {r1[0], r1[1]}, b3[2] = {r1[2], r1[3]};
        mma_f16(acc2[0], a, b0);
        mma_f16(acc2[1], a, b1);
        mma_f16(acc2[2], a, b2);
        mma_f16(acc2[3], a, b3);
    }

#pragma unroll
    for (int hh = 0; hh < 2; hh++) {
        int rr = w * 16 + g + hh * 8;
        if (rr < 49) {
            __half* orow = g_attn + (size_t)grow[rr] * CDIM + h * KD;
#pragma unroll
            for (int nj = 0; nj < 4; nj++) {
                int d = nj * 8 + 2 * t4;
                *(__half2*)(orow + d) =
                    __floats2half2_rn(acc2[nj][hh * 2 + 0], acc2[nj][hh * 2 + 1]);
            }
        }
    }
}

// ---------------- fused depthwise 3x3 conv + BN + LN2, 4 pixels/block (fp16 x1 in) ----
__global__ void __launch_bounds__(192) dwconv_bn_ln_kernel(const float* __restrict__ w,
                                                           const float* __restrict__ bg,
                                                           const float* __restrict__ bb,
                                                           const float* __restrict__ bmean,
                                                           const float* __restrict__ bvar,
                                                           const float* __restrict__ g2,
                                                           const float* __restrict__ b2)
{
    __shared__ float red[6][4];
    const int bid = blockIdx.x;
    const int cg  = bid % 14;
    const int tmp = bid / 14;
    const int r   = tmp % HW;
    const int bbi = tmp / HW;
    const int c0  = cg * 4;
    const int ch  = threadIdx.x;
    const int wd  = ch >> 5, lane = ch & 31;

    float w9[9];
#pragma unroll
    for (int i = 0; i < 9; i++) w9[i] = w[ch * 9 + i];

    float acc[4] = {0.f, 0.f, 0.f, 0.f};
#pragma unroll
    for (int kh = 0; kh < 3; kh++) {
        int rr = r + kh - 1;
        if (rr < 0 || rr >= HW) continue;
        const __half* rowb = g_x1 + ((size_t)bbi * 3136 + rr * HW) * CDIM + ch;
        float vals[6];
#pragma unroll
        for (int j = 0; j < 6; j++) {
            int col = c0 - 1 + j;
            vals[j] = (col >= 0 && col < HW) ? __half2float(rowb[(size_t)col * CDIM]) : 0.f;
        }
#pragma unroll
        for (int p = 0; p < 4; p++)
#pragma unroll
            for (int kw = 0; kw < 3; kw++)
                acc[p] += vals[p + kw] * w9[kh * 3 + kw];
    }

    const float inv = rsqrtf(bvar[ch] + 1e-5f);
    const float sc  = bg[ch] * inv;
    const float mu  = bmean[ch];
    const float bt  = bb[ch];
    float bnv[4];
#pragma unroll
    for (int p = 0; p < 4; p++) {
        bnv[p] = (acc[p] - mu) * sc + bt;
        g_x2[((size_t)bbi * 3136 + r * HW + c0 + p) * CDIM + ch] = bnv[p];
    }

    float s0 = bnv[0], s1 = bnv[1], s2 = bnv[2], s3 = bnv[3];
#pragma unroll
    for (int o = 16; o > 0; o >>= 1) {
        s0 += __shfl_xor_sync(0xffffffffu, s0, o);
        s1 += __shfl_xor_sync(0xffffffffu, s1, o);
        s2 += __shfl_xor_sync(0xffffffffu, s2, o);
        s3 += __shfl_xor_sync(0xffffffffu, s3, o);
    }
    if (lane == 0) { red[wd][0] = s0; red[wd][1] = s1; red[wd][2] = s2; red[wd][3] = s3; }
    __syncthreads();
    float mean[4];
#pragma unroll
    for (int p = 0; p < 4; p++)
        mean[p] = (red[0][p] + red[1][p] + red[2][p] + red[3][p] + red[4][p] + red[5][p]) * (1.0f / 192.0f);
    __syncthreads();

    float d[4];
    float q0, q1, q2, q3;
    d[0] = bnv[0] - mean[0]; q0 = d[0] * d[0];
    d[1] = bnv[1] - mean[1]; q1 = d[1] * d[1];
    d[2] = bnv[2] - mean[2]; q2 = d[2] * d[2];
    d[3] = bnv[3] - mean[3]; q3 = d[3] * d[3];
#pragma unroll
    for (int o = 16; o > 0; o >>= 1) {
        q0 += __shfl_xor_sync(0xffffffffu, q0, o);
        q1 += __shfl_xor_sync(0xffffffffu, q1, o);
        q2 += __shfl_xor_sync(0xffffffffu, q2, o);
        q3 += __shfl_xor_sync(0xffffffffu, q3, o);
    }
    if (lane == 0) { red[wd][0] = q0; red[wd][1] = q1; red[wd][2] = q2; red[wd][3] = q3; }
    __syncthreads();

    const float gg = g2[ch], b2v = b2[ch];
#pragma unroll
    for (int p = 0; p < 4; p++) {
        float var = (red[0][p] + red[1][p] + red[2][p] + red[3][p] + red[4][p] + red[5][p]) * (1.0f / 192.0f);
        float rstd = rsqrtf(var + 1e-5f);
        g_ln[((size_t)bbi * 3136 + r * HW + c0 + p) * CDIM + ch] =
            __float2half(d[p] * rstd * gg + b2v);
    }
}

// ---------------- launch ----------------
extern "C" void kernel_launch(void* const* d_in, const int* in_sizes, int n_in,
                              void* d_out, int out_size)
{
    (void)in_sizes; (void)n_in; (void)out_size;
    const float* x        = (const float*)d_in[0];
    const float* norm1_g  = (const float*)d_in[1];
    const float* norm1_b  = (const float*)d_in[2];
    const float* qkv_w    = (const float*)d_in[3];
    const float* qkv_b    = (const float*)d_in[4];
    const float* attnbias = (const float*)d_in[5];
    const float* proj_w   = (const float*)d_in[6];
    const float* proj_b   = (const float*)d_in[7];
    const float* conv_w   = (const float*)d_in[8];
    const float* bn_g     = (const float*)d_in[9];
    const float* bn_b     = (const float*)d_in[10];
    const float* bn_mean  = (const float*)d_in[11];
    const float* bn_var   = (const float*)d_in[12];
    const float* norm2_g  = (const float*)d_in[13];
    const float* norm2_b  = (const float*)d_in[14];
    const float* fc1_w    = (const float*)d_in[15];
    const float* fc1_b    = (const float*)d_in[16];
    const float* fc2_w    = (const float*)d_in[17];
    const float* fc2_b    = (const float*)d_in[18];
    float* out = (float*)d_out;

    __half *p_ln, *p_qkv, *p_attn, *p_mlp, *p_x1, *p_wt;
    float  *p_x2;
    cudaGetSymbolAddress((void**)&p_ln,   g_ln);
    cudaGetSymbolAddress((void**)&p_qkv,  g_qkv);
    cudaGetSymbolAddress((void**)&p_attn, g_attn);
    cudaGetSymbolAddress((void**)&p_mlp,  g_mlp);
    cudaGetSymbolAddress((void**)&p_x1,   g_x1);
    cudaGetSymbolAddress((void**)&p_x2,   g_x2);
    cudaGetSymbolAddress((void**)&p_wt,   g_wt);

    cudaFuncSetAttribute(gemm_h<0>, cudaFuncAttributeMaxDynamicSharedMemorySize, GT_SMEM);
    cudaFuncSetAttribute(gemm_h<1>, cudaFuncAttributeMaxDynamicSharedMemorySize, GT_SMEM);
    cudaFuncSetAttribute(gemm_h<2>, cudaFuncAttributeMaxDynamicSharedMemorySize, GT_SMEM);
    cudaFuncSetAttribute(gemm_h<3>, cudaFuncAttributeMaxDynamicSharedMemorySize, GT_SMEM);

    // 1) all weight transposes in one launch
    transpose_all<<<432, 256>>>(qkv_w, proj_w, fc1_w, fc2_w, p_wt);
    // 2) LN1
    ln_kernel<<<MROWS / 8, 256>>>(x, norm1_g, norm1_b, p_ln);
    // 3) QKV GEMM
    gemm_h<0><<<dim3(MROWS / 64, QKVN / 192), 256, GT_SMEM>>>(p_ln, p_wt + W_QKV, qkv_b, nullptr, p_qkv, QKVN, CDIM);
    // 4) windowed attention   [ncu sample lands here]
    attn_kernel<<<dim3(2048, NHEADS), 128>>>(attnbias);
    // 5) proj GEMM + residual x -> g_x1 (fp16)
    gemm_h<3><<<dim3(MROWS / 64, 1), 256, GT_SMEM>>>(p_attn, p_wt + W_PROJ, proj_b, x, p_x1, CDIM, CDIM);
    // 6) depthwise conv + BN + LN2 (fused, 4 px/block, fp16 x1)
    dwconv_bn_ln_kernel<<<32 * HW * (HW / 4), CDIM>>>(conv_w, bn_g, bn_b, bn_mean, bn_var, norm2_g, norm2_b);
    // 7) fc1 GEMM + GELU -> g_mlp (fp16)
    gemm_h<1><<<dim3(MROWS / 64, HID / 192), 256, GT_SMEM>>>(p_ln, p_wt + W_FC1, fc1_b, nullptr, p_mlp, HID, CDIM);
    // 8) fc2 GEMM + residual x2 -> out (f32)
    gemm_h<2><<<dim3(MROWS / 64, 1), 256, GT_SMEM>>>(p_mlp, p_wt + W_FC2, fc2_b, p_x2, out, CDIM, HID);
}

// round 14
// speedup vs baseline: 1.1500x; 1.0815x over previous
#include <cuda_runtime.h>
#include <cuda_fp16.h>
#include <math.h>
#include <stdint.h>

// ---------------- constants ----------------
#define MROWS  100352      // 32 * 3136
#define CDIM   192
#define NHEADS 6
#define KD     32
#define QKVN   576
#define HID    768
#define HW     56

// transposed fp16 weight scratch offsets (all [N,K] K-major)
#define W_QKV  0
#define W_PROJ 110592
#define W_FC1  147456
#define W_FC2  294912
#define W_TOT  442368

// ---------------- scratch ----------------
__device__ __half g_ln  [(size_t)MROWS * CDIM];
__device__ __half g_qkv [(size_t)MROWS * QKVN];
__device__ __half g_attn[(size_t)MROWS * CDIM];
__device__ __half g_mlp [(size_t)MROWS * HID];
__device__ __half g_x1  [(size_t)MROWS * CDIM];
__device__ float  g_x2  [(size_t)MROWS * CDIM];
__device__ __half g_wt  [W_TOT];

// ---------------- helpers ----------------
__device__ __forceinline__ uint32_t smem_u32(const void* p) {
    uint32_t a;
    asm("{ .reg .u64 t; cvta.to.shared.u64 t, %1; cvt.u32.u64 %0, t; }" : "=r"(a) : "l"(p));
    return a;
}

__device__ __forceinline__ void cp16s(uint32_t s, const void* g) {
    asm volatile("cp.async.ca.shared.global [%0], [%1], 16;" :: "r"(s), "l"(g));
}

__device__ __forceinline__ void ldsm4(uint32_t* r, uint32_t addr) {
    asm volatile("ldmatrix.sync.aligned.m8n8.x4.shared.b16 {%0,%1,%2,%3}, [%4];"
                 : "=r"(r[0]), "=r"(r[1]), "=r"(r[2]), "=r"(r[3]) : "r"(addr));
}

__device__ __forceinline__ void ldsm4t(uint32_t* r, uint32_t addr) {
    asm volatile("ldmatrix.sync.aligned.m8n8.x4.trans.shared.b16 {%0,%1,%2,%3}, [%4];"
                 : "=r"(r[0]), "=r"(r[1]), "=r"(r[2]), "=r"(r[3]) : "r"(addr));
}

__device__ __forceinline__ void mma_f16(float* d, const uint32_t* a, const uint32_t* b) {
    asm volatile(
        "mma.sync.aligned.m16n8k16.row.col.f32.f16.f16.f32 "
        "{%0,%1,%2,%3}, {%4,%5,%6,%7}, {%8,%9}, {%0,%1,%2,%3};"
        : "+f"(d[0]), "+f"(d[1]), "+f"(d[2]), "+f"(d[3])
        : "r"(a[0]), "r"(a[1]), "r"(a[2]), "r"(a[3]), "r"(b[0]), "r"(b[1]));
}

// ---------------- merged weight transpose: 4 tensors in one launch ----------------
__global__ void __launch_bounds__(256) transpose_all(const float* __restrict__ qkv_w,
                                                     const float* __restrict__ proj_w,
                                                     const float* __restrict__ fc1_w,
                                                     const float* __restrict__ fc2_w,
                                                     __half* __restrict__ wt)
{
    __shared__ float t[32][33];
    int bid = blockIdx.x;
    const float* src; __half* dst; int Kdim, Ndim, bx, by;
    if (bid < 108)      { src = qkv_w;  dst = wt + W_QKV;  Kdim = CDIM; Ndim = QKVN; int q = bid;       bx = q % 18; by = q / 18; }
    else if (bid < 144) { src = proj_w; dst = wt + W_PROJ; Kdim = CDIM; Ndim = CDIM; int q = bid - 108; bx = q % 6;  by = q / 6; }
    else if (bid < 288) { src = fc1_w;  dst = wt + W_FC1;  Kdim = CDIM; Ndim = HID;  int q = bid - 144; bx = q % 24; by = q / 24; }
    else                { src = fc2_w;  dst = wt + W_FC2;  Kdim = HID;  Ndim = CDIM; int q = bid - 288; bx = q % 6;  by = q / 6; }

    int n0 = bx * 32, k0 = by * 32;
    int tx = threadIdx.x & 31, ty = threadIdx.x >> 5;
#pragma unroll
    for (int i = ty; i < 32; i += 8)
        t[i][tx] = src[(size_t)(k0 + i) * Ndim + n0 + tx];
    __syncthreads();
#pragma unroll
    for (int i = ty; i < 32; i += 8)
        dst[(size_t)(n0 + i) * Kdim + k0 + tx] = __float2half(t[tx][i]);
}

// ---------------- LayerNorm (LN1): fp16 output ----------------
__global__ void __launch_bounds__(256) ln_kernel(const float* __restrict__ x,
                                                 const float* __restrict__ g,
                                                 const float* __restrict__ b,
                                                 __half* __restrict__ out)
{
    int warp = threadIdx.x >> 5;
    int lane = threadIdx.x & 31;
    long row = (long)blockIdx.x * 8 + warp;
    const float* xr = x + row * CDIM;

    float v[6];
#pragma unroll
    for (int i = 0; i < 6; i++) v[i] = xr[lane + 32 * i];

    float s = 0.f;
#pragma unroll
    for (int i = 0; i < 6; i++) s += v[i];
#pragma unroll
    for (int o = 16; o > 0; o >>= 1) s += __shfl_xor_sync(0xffffffffu, s, o);
    float mean = s * (1.0f / 192.0f);

    float sq = 0.f;
#pragma unroll
    for (int i = 0; i < 6; i++) { float d = v[i] - mean; sq += d * d; }
#pragma unroll
    for (int o = 16; o > 0; o >>= 1) sq += __shfl_xor_sync(0xffffffffu, sq, o);
    float rstd = rsqrtf(sq * (1.0f / 192.0f) + 1e-5f);

    __half* orow = out + row * CDIM;
#pragma unroll
    for (int i = 0; i < 6; i++) {
        int c = lane + 32 * i;
        orow[c] = __float2half((v[i] - mean) * rstd * g[c] + b[c]);
    }
}

// ---------------- FP16 mma GEMM: BM=64, BN=192, BK=64, 3-stage, 2 CTAs/SM ----------------
// EPI: 0 bias->fp16 | 1 bias+GELU->fp16 | 2 bias+res(f32)->f32 | 3 bias+res(f32)->fp16
#define GT_BOFF  8192
#define GT_STAGE 32768
#define GT_SMEM  (3 * GT_STAGE)

template <int EPI>
__global__ void __launch_bounds__(256, 2) gemm_h(const __half* __restrict__ A,
                                                 const __half* __restrict__ BT,
                                                 const float* __restrict__ bias,
                                                 const float* __restrict__ res,
                                                 void* __restrict__ Cout,
                                                 int N, int K)
{
    extern __shared__ char smem[];
    const uint32_t sb = smem_u32(smem);

    const int tid  = threadIdx.x;
    const int wid  = tid >> 5, lane = tid & 31;
    const int wm   = wid & 1,  wn   = wid >> 1;
    const int g    = lane >> 2, t4  = lane & 3;
    const int lg   = lane >> 3, lr  = lane & 7;
    const long m0  = (long)blockIdx.x * 64;
    const int  n0  = blockIdx.y * 192;
    const int  T   = K >> 6;

    float acc[2][6][4];
#pragma unroll
    for (int mi = 0; mi < 2; mi++)
#pragma unroll
        for (int nj = 0; nj < 6; nj++)
#pragma unroll
            for (int r = 0; r < 4; r++) acc[mi][nj][r] = 0.f;

    uint32_t pA[2], xA[2];
#pragma unroll
    for (int mi = 0; mi < 2; mi++) {
        int row = wm * 32 + mi * 16 + (lg & 1) * 8 + lr;
        pA[mi] = (uint32_t)row * 128;
        xA[mi] = (uint32_t)(row & 7) * 16;
    }
    const uint32_t hiA = (uint32_t)(lg >> 1) * 16;
    uint32_t pB[3], xB[3];
#pragma unroll
    for (int p = 0; p < 3; p++) {
        int row = wn * 48 + p * 16 + ((lg >> 1) & 1) * 8 + lr;
        pB[p] = (uint32_t)row * 128;
        xB[p] = (uint32_t)(row & 7) * 16;
    }
    const uint32_t hiB = (uint32_t)(lg & 1) * 16;

    auto load_stage = [&](int t, int st) {
        const uint32_t sa = sb + (uint32_t)st * GT_STAGE;
        const int kf = t << 6;
#pragma unroll
        for (int i = 0; i < 2; i++) {
            int q = tid + i * 256;
            int row = q >> 3, ch = q & 7;
            cp16s(sa + (uint32_t)row * 128 + (uint32_t)((ch ^ (row & 7)) * 16),
                  A + (m0 + row) * (size_t)K + kf + ch * 8);
        }
#pragma unroll
        for (int i = 0; i < 6; i++) {
            int q = tid + i * 256;
            int row = q >> 3, ch = q & 7;
            cp16s(sa + GT_BOFF + (uint32_t)row * 128 + (uint32_t)((ch ^ (row & 7)) * 16),
                  BT + (size_t)(n0 + row) * K + kf + ch * 8);
        }
    };

    load_stage(0, 0);
    asm volatile("cp.async.commit_group;");
    load_stage(1, 1);
    asm volatile("cp.async.commit_group;");

    for (int t = 0; t < T; t++) {
        if (t + 2 < T) load_stage(t + 2, (t + 2) % 3);
        asm volatile("cp.async.commit_group;");
        asm volatile("cp.async.wait_group 2;");
        __syncthreads();

        const uint32_t sa  = sb + (uint32_t)(t % 3) * GT_STAGE;
        const uint32_t sbB = sa + GT_BOFF;
#pragma unroll
        for (int s = 0; s < 4; s++) {
            const uint32_t cs = (uint32_t)(s * 32);
            uint32_t a[2][4], b[6][2];
#pragma unroll
            for (int mi = 0; mi < 2; mi++)
                ldsm4(a[mi], sa + pA[mi] + ((cs + hiA) ^ xA[mi]));
#pragma unroll
            for (int p = 0; p < 3; p++) {
                uint32_t r[4];
                ldsm4(r, sbB + pB[p] + ((cs + hiB) ^ xB[p]));
                b[2 * p][0]     = r[0]; b[2 * p][1]     = r[1];
                b[2 * p + 1][0] = r[2]; b[2 * p + 1][1] = r[3];
            }
#pragma unroll
            for (int mi = 0; mi < 2; mi++)
#pragma unroll
                for (int nj = 0; nj < 6; nj++)
                    mma_f16(acc[mi][nj], a[mi], b[nj]);
        }
        __syncthreads();
    }

#pragma unroll
    for (int mi = 0; mi < 2; mi++) {
#pragma unroll
        for (int half = 0; half < 2; half++) {
            long r = m0 + wm * 32 + mi * 16 + g + half * 8;
#pragma unroll
            for (int nj = 0; nj < 6; nj++) {
                int cb = n0 + wn * 48 + nj * 8 + 2 * t4;
                float o0 = acc[mi][nj][half * 2 + 0] + __ldg(bias + cb);
                float o1 = acc[mi][nj][half * 2 + 1] + __ldg(bias + cb + 1);
                if (EPI == 1) {
                    o0 = 0.5f * o0 * (1.0f + erff(o0 * 0.7071067811865476f));
                    o1 = 0.5f * o1 * (1.0f + erff(o1 * 0.7071067811865476f));
                }
                if (EPI == 2 || EPI == 3) {
                    const float2 rv = *(const float2*)(res + r * (size_t)N + cb);
                    o0 += rv.x; o1 += rv.y;
                }
                if (EPI == 2) {
                    *(float2*)((float*)Cout + r * (size_t)N + cb) = make_float2(o0, o1);
                } else {
                    __half2 hv = __floats2half2_rn(o0, o1);
                    *(__half2*)((__half*)Cout + r * (size_t)N + cb) = hv;
                }
            }
        }
    }
}

// ---------------- Windowed attention: tensor cores + register softmax ----------------
#define AP 40
#define PP 72

__global__ void __launch_bounds__(128, 6) attn_kernel(const float* __restrict__ attn_bias)
{
    __shared__ __half qs[64 * AP];
    __shared__ __half ks[64 * AP];
    __shared__ __half vs[64 * AP];
    __shared__ __half P [64 * PP];
    __shared__ float  bh[49];
    __shared__ int    grow[49];

    const int tid = threadIdx.x;
    const int w   = tid >> 5, lane = tid & 31;
    const int g   = lane >> 2, t4 = lane & 3;
    const int lg  = lane >> 3, lr = lane & 7;
    const int wid = blockIdx.x;
    const int h   = blockIdx.y;
    const int b   = wid >> 6;
    const int wr  = wid & 63;
    const int wy  = wr >> 3, wx = wr & 7;

    const uint32_t qsb = smem_u32(qs), ksb = smem_u32(ks), vsb = smem_u32(vs);
    const uint32_t Pb  = smem_u32(P);

    if (tid < 49) {
        int ty = tid / 7, tx = tid - ty * 7;
        grow[tid] = b * 3136 + (wy * 7 + ty) * HW + (wx * 7 + tx);
        bh[tid]   = attn_bias[h * 49 + tid];
    }
    // zero only vs pad rows 49..63 (P·V hazard: P pad cols are exact zeros,
    // but 0 x garbage-Inf would be NaN). qs/ks pads feed only discarded S entries.
    {
        uint32_t* z = (uint32_t*)vs;
        for (int i = tid; i < 300; i += 128) z[980 + i] = 0;   // rows 49..63 x 80B
    }
    __syncthreads();

    for (int i = tid; i < 588; i += 128) {
        int t = i / 12;
        int rm = i - t * 12;
        int tensor = rm >> 2, ch = rm & 3;
        const __half* src = g_qkv + (size_t)grow[t] * QKVN + h * 96 + tensor * 32 + ch * 8;
        uint32_t base = (tensor == 0) ? qsb : (tensor == 1) ? ksb : vsb;
        cp16s(base + (uint32_t)t * 80 + (uint32_t)ch * 16, src);
    }
    asm volatile("cp.async.commit_group;");
    asm volatile("cp.async.wait_group 0;");
    __syncthreads();

    // ---- S = Q K^T ----
    float acc[8][4];
#pragma unroll
    for (int nj = 0; nj < 8; nj++)
#pragma unroll
        for (int r = 0; r < 4; r++) acc[nj][r] = 0.f;

    const uint32_t aaddr = qsb + (uint32_t)(w * 16 + (lg & 1) * 8 + lr) * 80 + (uint32_t)(lg >> 1) * 16;
    const uint32_t baddr = ksb + (uint32_t)(((lg >> 1) & 1) * 8 + lr) * 80 + (uint32_t)(lg & 1) * 16;
#pragma unroll
    for (int s = 0; s < 2; s++) {
        uint32_t a[4];
        ldsm4(a, aaddr + s * 32);
#pragma unroll
        for (int p = 0; p < 4; p++) {
            uint32_t r[4];
            ldsm4(r, baddr + (uint32_t)p * (16 * 80) + s * 32);
            uint32_t b0[2] = {r[0], r[1]}, b1[2] = {r[2], r[3]};
            mma_f16(acc[2 * p], a, b0);
            mma_f16(acc[2 * p + 1], a, b1);
        }
    }

    // ---- scale + bias + softmax in registers (row = quad; cols spread over t4) ----
    const float scale = 0.17677669529663687f;
#pragma unroll
    for (int hh = 0; hh < 2; hh++) {
        const int rr = w * 16 + g + hh * 8;
        const int rn = rr / 7, cn = rr - rn * 7;
        float v[16];
        float mx = -1e30f;
#pragma unroll
        for (int nj = 0; nj < 8; nj++) {
#pragma unroll
            for (int q = 0; q < 2; q++) {
                int cc = nj * 8 + 2 * t4 + q;
                float val = -1e30f;
                if (rr < 49 && cc < 49) {
                    int rm2 = cc / 7, cm2 = cc - rm2 * 7;
                    val = acc[nj][hh * 2 + q] * scale + bh[abs(rn - rm2) * 7 + abs(cn - cm2)];
                }
                v[nj * 2 + q] = val;
                mx = fmaxf(mx, val);
            }
        }
        mx = fmaxf(mx, __shfl_xor_sync(0xffffffffu, mx, 1));
        mx = fmaxf(mx, __shfl_xor_sync(0xffffffffu, mx, 2));
        float sum = 0.f;
#pragma unroll
        for (int i = 0; i < 16; i++) { v[i] = __expf(v[i] - mx); sum += v[i]; }
        sum += __shfl_xor_sync(0xffffffffu, sum, 1);
        sum += __shfl_xor_sync(0xffffffffu, sum, 2);
        const float inv = 1.0f / sum;
#pragma unroll
        for (int nj = 0; nj < 8; nj++) {
            __half2 hv = __floats2half2_rn(v[nj * 2] * inv, v[nj * 2 + 1] * inv);
            *(__half2*)((__half*)P + rr * PP + nj * 8 + 2 * t4) = hv;
        }
    }
    __syncthreads();

    // ---- O = P V ----
    float acc2[4][4];
#pragma unroll
    for (int nj = 0; nj < 4; nj++)
#pragma unroll
        for (int r = 0; r < 4; r++) acc2[nj][r] = 0.f;

    const uint32_t paddr = Pb + (uint32_t)(w * 16 + (lg & 1) * 8 + lr) * 144 + (uint32_t)(lg >> 1) * 16;
    const uint32_t vaddr = vsb + (uint32_t)((lg & 1) * 8 + lr) * 80 + (uint32_t)(lg >> 1) * 16;
#pragma unroll
    for (int s = 0; s < 4; s++) {
        uint32_t a[4];
        ldsm4(a, paddr + s * 32);
        uint32_t r0[4], r1[4];
        ldsm4t(r0, vaddr + (uint32_t)s * (16 * 80));
        ldsm4t(r1, vaddr + (uint32_t)s * (16 * 80) + 32);
        uint32_t b0[2] = {r0[0], r0[1]}, b1[2] = {r0[2], r0[3]};
        uint32_t b2[2] = {r1[0], r1[1]}, b3[2] = {r1[2], r1[3]};
        mma_f16(acc2[0], a, b0);
        mma_f16(acc2[1], a, b1);
        mma_f16(acc2[2], a, b2);
        mma_f16(acc2[3], a, b3);
    }

#pragma unroll
    for (int hh = 0; hh < 2; hh++) {
        int rr = w * 16 + g + hh * 8;
        if (rr < 49) {
            __half* orow = g_attn + (size_t)grow[rr] * CDIM + h * KD;
#pragma unroll
            for (int nj = 0; nj < 4; nj++) {
                int d = nj * 8 + 2 * t4;
                *(__half2*)(orow + d) =
                    __floats2half2_rn(acc2[nj][hh * 2 + 0], acc2[nj][hh * 2 + 1]);
            }
        }
    }
}

// ---------------- fused depthwise 3x3 conv + BN + LN2, 4 pixels/block (fp16 x1 in) ----
__global__ void __launch_bounds__(192) dwconv_bn_ln_kernel(const float* __restrict__ w,
                                                           const float* __restrict__ bg,
                                                           const float* __restrict__ bb,
                                                           const float* __restrict__ bmean,
                                                           const float* __restrict__ bvar,
                                                           const float* __restrict__ g2,
                                                           const float* __restrict__ b2)
{
    __shared__ float red[6][4];
    const int bid = blockIdx.x;
    const int cg  = bid % 14;
    const int tmp = bid / 14;
    const int r   = tmp % HW;
    const int bbi = tmp / HW;
    const int c0  = cg * 4;
    const int ch  = threadIdx.x;
    const int wd  = ch >> 5, lane = ch & 31;

    float w9[9];
#pragma unroll
    for (int i = 0; i < 9; i++) w9[i] = w[ch * 9 + i];

    float acc[4] = {0.f, 0.f, 0.f, 0.f};
#pragma unroll
    for (int kh = 0; kh < 3; kh++) {
        int rr = r + kh - 1;
        if (rr < 0 || rr >= HW) continue;
        const __half* rowb = g_x1 + ((size_t)bbi * 3136 + rr * HW) * CDIM + ch;
        float vals[6];
#pragma unroll
        for (int j = 0; j < 6; j++) {
            int col = c0 - 1 + j;
            vals[j] = (col >= 0 && col < HW) ? __half2float(rowb[(size_t)col * CDIM]) : 0.f;
        }
#pragma unroll
        for (int p = 0; p < 4; p++)
#pragma unroll
            for (int kw = 0; kw < 3; kw++)
                acc[p] += vals[p + kw] * w9[kh * 3 + kw];
    }

    const float inv = rsqrtf(bvar[ch] + 1e-5f);
    const float sc  = bg[ch] * inv;
    const float mu  = bmean[ch];
    const float bt  = bb[ch];
    float bnv[4];
#pragma unroll
    for (int p = 0; p < 4; p++) {
        bnv[p] = (acc[p] - mu) * sc + bt;
        g_x2[((size_t)bbi * 3136 + r * HW + c0 + p) * CDIM + ch] = bnv[p];
    }

    float s0 = bnv[0], s1 = bnv[1], s2 = bnv[2], s3 = bnv[3];
#pragma unroll
    for (int o = 16; o > 0; o >>= 1) {
        s0 += __shfl_xor_sync(0xffffffffu, s0, o);
        s1 += __shfl_xor_sync(0xffffffffu, s1, o);
        s2 += __shfl_xor_sync(0xffffffffu, s2, o);
        s3 += __shfl_xor_sync(0xffffffffu, s3, o);
    }
    if (lane == 0) { red[wd][0] = s0; red[wd][1] = s1; red[wd][2] = s2; red[wd][3] = s3; }
    __syncthreads();
    float mean[4];
#pragma unroll
    for (int p = 0; p < 4; p++)
        mean[p] = (red[0][p] + red[1][p] + red[2][p] + red[3][p] + red[4][p] + red[5][p]) * (1.0f / 192.0f);
    __syncthreads();

    float d[4];
    float q0, q1, q2, q3;
    d[0] = bnv[0] - mean[0]; q0 = d[0] * d[0];
    d[1] = bnv[1] - mean[1]; q1 = d[1] * d[1];
    d[2] = bnv[2] - mean[2]; q2 = d[2] * d[2];
    d[3] = bnv[3] - mean[3]; q3 = d[3] * d[3];
#pragma unroll
    for (int o = 16; o > 0; o >>= 1) {
        q0 += __shfl_xor_sync(0xffffffffu, q0, o);
        q1 += __shfl_xor_sync(0xffffffffu, q1, o);
        q2 += __shfl_xor_sync(0xffffffffu, q2, o);
        q3 += __shfl_xor_sync(0xffffffffu, q3, o);
    }
    if (lane == 0) { red[wd][0] = q0; red[wd][1] = q1; red[wd][2] = q2; red[wd][3] = q3; }
    __syncthreads();

    const float gg = g2[ch], b2v = b2[ch];
#pragma unroll
    for (int p = 0; p < 4; p++) {
        float var = (red[0][p] + red[1][p] + red[2][p] + red[3][p] + red[4][p] + red[5][p]) * (1.0f / 192.0f);
        float rstd = rsqrtf(var + 1e-5f);
        g_ln[((size_t)bbi * 3136 + r * HW + c0 + p) * CDIM + ch] =
            __float2half(d[p] * rstd * gg + b2v);
    }
}

// ---------------- launch ----------------
extern "C" void kernel_launch(void* const* d_in, const int* in_sizes, int n_in,
                              void* d_out, int out_size)
{
    (void)in_sizes; (void)n_in; (void)out_size;
    const float* x        = (const float*)d_in[0];
    const float* norm1_g  = (const float*)d_in[1];
    const float* norm1_b  = (const float*)d_in[2];
    const float* qkv_w    = (const float*)d_in[3];
    const float* qkv_b    = (const float*)d_in[4];
    const float* attnbias = (const float*)d_in[5];
    const float* proj_w   = (const float*)d_in[6];
    const float* proj_b   = (const float*)d_in[7];
    const float* conv_w   = (const float*)d_in[8];
    const float* bn_g     = (const float*)d_in[9];
    const float* bn_b     = (const float*)d_in[10];
    const float* bn_mean  = (const float*)d_in[11];
    const float* bn_var   = (const float*)d_in[12];
    const float* norm2_g  = (const float*)d_in[13];
    const float* norm2_b  = (const float*)d_in[14];
    const float* fc1_w    = (const float*)d_in[15];
    const float* fc1_b    = (const float*)d_in[16];
    const float* fc2_w    = (const float*)d_in[17];
    const float* fc2_b    = (const float*)d_in[18];
    float* out = (float*)d_out;

    __half *p_ln, *p_qkv, *p_attn, *p_mlp, *p_x1, *p_wt;
    float  *p_x2;
    cudaGetSymbolAddress((void**)&p_ln,   g_ln);
    cudaGetSymbolAddress((void**)&p_qkv,  g_qkv);
    cudaGetSymbolAddress((void**)&p_attn, g_attn);
    cudaGetSymbolAddress((void**)&p_mlp,  g_mlp);
    cudaGetSymbolAddress((void**)&p_x1,   g_x1);
    cudaGetSymbolAddress((void**)&p_x2,   g_x2);
    cudaGetSymbolAddress((void**)&p_wt,   g_wt);

    cudaFuncSetAttribute(gemm_h<0>, cudaFuncAttributeMaxDynamicSharedMemorySize, GT_SMEM);
    cudaFuncSetAttribute(gemm_h<1>, cudaFuncAttributeMaxDynamicSharedMemorySize, GT_SMEM);
    cudaFuncSetAttribute(gemm_h<2>, cudaFuncAttributeMaxDynamicSharedMemorySize, GT_SMEM);
    cudaFuncSetAttribute(gemm_h<3>, cudaFuncAttributeMaxDynamicSharedMemorySize, GT_SMEM);

    // 1) all weight transposes in one launch
    transpose_all<<<432, 256>>>(qkv_w, proj_w, fc1_w, fc2_w, p_wt);
    // 2) LN1
    ln_kernel<<<MROWS / 8, 256>>>(x, norm1_g, norm1_b, p_ln);
    // 3) QKV GEMM
    gemm_h<0><<<dim3(MROWS / 64, QKVN / 192), 256, GT_SMEM>>>(p_ln, p_wt + W_QKV, qkv_b, nullptr, p_qkv, QKVN, CDIM);
    // 4) windowed attention (register softmax)   [ncu sample lands here]
    attn_kernel<<<dim3(2048, NHEADS), 128>>>(attnbias);
    // 5) proj GEMM + residual x -> g_x1 (fp16)
    gemm_h<3><<<dim3(MROWS / 64, 1), 256, GT_SMEM>>>(p_attn, p_wt + W_PROJ, proj_b, x, p_x1, CDIM, CDIM);
    // 6) depthwise conv + BN + LN2 (fused, 4 px/block, fp16 x1)
    dwconv_bn_ln_kernel<<<32 * HW * (HW / 4), CDIM>>>(conv_w, bn_g, bn_b, bn_mean, bn_var, norm2_g, norm2_b);
    // 7) fc1 GEMM + GELU -> g_mlp (fp16)
    gemm_h<1><<<dim3(MROWS / 64, HID / 192), 256, GT_SMEM>>>(p_ln, p_wt + W_FC1, fc1_b, nullptr, p_mlp, HID, CDIM);
    // 8) fc2 GEMM + residual x2 -> out (f32)
    gemm_h<2><<<dim3(MROWS / 64, 1), 256, GT_SMEM>>>(p_mlp, p_wt + W_FC2, fc2_b, p_x2, out, CDIM, HID);
}

// round 15
// speedup vs baseline: 1.1634x; 1.0117x over previous
#include <cuda_runtime.h>
#include <cuda_fp16.h>
#include <math.h>
#include <stdint.h>

// ---------------- constants ----------------
#define MROWS  100352      // 32 * 3136
#define CDIM   192
#define NHEADS 6
#define KD     32
#define QKVN   576
#define HID    768
#define HW     56

// transposed fp16 weight scratch offsets (all [N,K] K-major)
#define W_QKV  0
#define W_PROJ 110592
#define W_FC1  147456
#define W_FC2  294912
#define W_TOT  442368

// ---------------- scratch ----------------
__device__ __half g_ln   [(size_t)MROWS * CDIM];
__device__ __half g_qkv  [(size_t)MROWS * QKVN];
__device__ __half g_attn [(size_t)MROWS * CDIM];
__device__ __half g_mlp  [(size_t)MROWS * HID];
__device__ __half g_x1   [(size_t)MROWS * CDIM];
__device__ float  g_x2   [(size_t)MROWS * CDIM];
__device__ __half g_wt   [W_TOT];
__device__ __half g_biasx[NHEADS * 49 * 64];       // expanded bias, cols>=49 = -65504

// ---------------- helpers ----------------
__device__ __forceinline__ uint32_t smem_u32(const void* p) {
    uint32_t a;
    asm("{ .reg .u64 t; cvta.to.shared.u64 t, %1; cvt.u32.u64 %0, t; }" : "=r"(a) : "l"(p));
    return a;
}

__device__ __forceinline__ void cp16s(uint32_t s, const void* g) {
    asm volatile("cp.async.ca.shared.global [%0], [%1], 16;" :: "r"(s), "l"(g));
}

__device__ __forceinline__ void ldsm4(uint32_t* r, uint32_t addr) {
    asm volatile("ldmatrix.sync.aligned.m8n8.x4.shared.b16 {%0,%1,%2,%3}, [%4];"
                 : "=r"(r[0]), "=r"(r[1]), "=r"(r[2]), "=r"(r[3]) : "r"(addr));
}

__device__ __forceinline__ void ldsm4t(uint32_t* r, uint32_t addr) {
    asm volatile("ldmatrix.sync.aligned.m8n8.x4.trans.shared.b16 {%0,%1,%2,%3}, [%4];"
                 : "=r"(r[0]), "=r"(r[1]), "=r"(r[2]), "=r"(r[3]) : "r"(addr));
}

__device__ __forceinline__ void mma_f16(float* d, const uint32_t* a, const uint32_t* b) {
    asm volatile(
        "mma.sync.aligned.m16n8k16.row.col.f32.f16.f16.f32 "
        "{%0,%1,%2,%3}, {%4,%5,%6,%7}, {%8,%9}, {%0,%1,%2,%3};"
        : "+f"(d[0]), "+f"(d[1]), "+f"(d[2]), "+f"(d[3])
        : "r"(a[0]), "r"(a[1]), "r"(a[2]), "r"(a[3]), "r"(b[0]), "r"(b[1]));
}

// ---------------- prep: weight transposes + bias expansion + LN1, one launch ----------
// blocks [0,432): transposes; [432,438): bias expand; [438,12982): LN1 (8 rows each)
__global__ void __launch_bounds__(256) prep_kernel(const float* __restrict__ qkv_w,
                                                   const float* __restrict__ proj_w,
                                                   const float* __restrict__ fc1_w,
                                                   const float* __restrict__ fc2_w,
                                                   __half* __restrict__ wt,
                                                   const float* __restrict__ attn_bias,
                                                   __half* __restrict__ biasx,
                                                   const float* __restrict__ x,
                                                   const float* __restrict__ g1,
                                                   const float* __restrict__ b1,
                                                   __half* __restrict__ lnout)
{
    int bid = blockIdx.x;
    if (bid < 432) {
        __shared__ float t[32][33];
        const float* src; __half* dst; int Kdim, Ndim, bx, by;
        if (bid < 108)      { src = qkv_w;  dst = wt + W_QKV;  Kdim = CDIM; Ndim = QKVN; int q = bid;       bx = q % 18; by = q / 18; }
        else if (bid < 144) { src = proj_w; dst = wt + W_PROJ; Kdim = CDIM; Ndim = CDIM; int q = bid - 108; bx = q % 6;  by = q / 6; }
        else if (bid < 288) { src = fc1_w;  dst = wt + W_FC1;  Kdim = CDIM; Ndim = HID;  int q = bid - 144; bx = q % 24; by = q / 24; }
        else                { src = fc2_w;  dst = wt + W_FC2;  Kdim = HID;  Ndim = CDIM; int q = bid - 288; bx = q % 6;  by = q / 6; }

        int n0 = bx * 32, k0 = by * 32;
        int tx = threadIdx.x & 31, ty = threadIdx.x >> 5;
#pragma unroll
        for (int i = ty; i < 32; i += 8)
            t[i][tx] = src[(size_t)(k0 + i) * Ndim + n0 + tx];
        __syncthreads();
#pragma unroll
        for (int i = ty; i < 32; i += 8)
            dst[(size_t)(n0 + i) * Kdim + k0 + tx] = __float2half(t[tx][i]);
    } else if (bid < 438) {
        const int h = bid - 432;
        for (int i = threadIdx.x; i < 49 * 64; i += 256) {
            int n = i >> 6, m = i & 63;
            float v = -65504.f;
            if (m < 49) {
                int rn = n / 7, cn = n - rn * 7;
                int rm = m / 7, cm = m - rm * 7;
                v = attn_bias[h * 49 + abs(rn - rm) * 7 + abs(cn - cm)];
            }
            biasx[h * 3136 + i] = __float2half(v);
        }
    } else {
        int warp = threadIdx.x >> 5;
        int lane = threadIdx.x & 31;
        long row = (long)(bid - 438) * 8 + warp;
        const float* xr = x + row * CDIM;

        float v[6];
#pragma unroll
        for (int i = 0; i < 6; i++) v[i] = xr[lane + 32 * i];

        float s = 0.f;
#pragma unroll
        for (int i = 0; i < 6; i++) s += v[i];
#pragma unroll
        for (int o = 16; o > 0; o >>= 1) s += __shfl_xor_sync(0xffffffffu, s, o);
        float mean = s * (1.0f / 192.0f);

        float sq = 0.f;
#pragma unroll
        for (int i = 0; i < 6; i++) { float d = v[i] - mean; sq += d * d; }
#pragma unroll
        for (int o = 16; o > 0; o >>= 1) sq += __shfl_xor_sync(0xffffffffu, sq, o);
        float rstd = rsqrtf(sq * (1.0f / 192.0f) + 1e-5f);

        __half* orow = lnout + row * CDIM;
#pragma unroll
        for (int i = 0; i < 6; i++) {
            int c = lane + 32 * i;
            orow[c] = __float2half((v[i] - mean) * rstd * g1[c] + b1[c]);
        }
    }
}

// ---------------- FP16 mma GEMM: BM=64, BN=192, BK=64, 3-stage, 2 CTAs/SM ----------------
// EPI: 0 bias->fp16 | 1 bias+GELU->fp16 | 2 bias+res(f32)->f32 | 3 bias+res(f32)->fp16
#define GT_BOFF  8192
#define GT_STAGE 32768
#define GT_SMEM  (3 * GT_STAGE)

template <int EPI>
__global__ void __launch_bounds__(256, 2) gemm_h(const __half* __restrict__ A,
                                                 const __half* __restrict__ BT,
                                                 const float* __restrict__ bias,
                                                 const float* __restrict__ res,
                                                 void* __restrict__ Cout,
                                                 int N, int K)
{
    extern __shared__ char smem[];
    const uint32_t sb = smem_u32(smem);

    const int tid  = threadIdx.x;
    const int wid  = tid >> 5, lane = tid & 31;
    const int wm   = wid & 1,  wn   = wid >> 1;
    const int g    = lane >> 2, t4  = lane & 3;
    const int lg   = lane >> 3, lr  = lane & 7;
    const long m0  = (long)blockIdx.x * 64;
    const int  n0  = blockIdx.y * 192;
    const int  T   = K >> 6;

    float acc[2][6][4];
#pragma unroll
    for (int mi = 0; mi < 2; mi++)
#pragma unroll
        for (int nj = 0; nj < 6; nj++)
#pragma unroll
            for (int r = 0; r < 4; r++) acc[mi][nj][r] = 0.f;

    uint32_t pA[2], xA[2];
#pragma unroll
    for (int mi = 0; mi < 2; mi++) {
        int row = wm * 32 + mi * 16 + (lg & 1) * 8 + lr;
        pA[mi] = (uint32_t)row * 128;
        xA[mi] = (uint32_t)(row & 7) * 16;
    }
    const uint32_t hiA = (uint32_t)(lg >> 1) * 16;
    uint32_t pB[3], xB[3];
#pragma unroll
    for (int p = 0; p < 3; p++) {
        int row = wn * 48 + p * 16 + ((lg >> 1) & 1) * 8 + lr;
        pB[p] = (uint32_t)row * 128;
        xB[p] = (uint32_t)(row & 7) * 16;
    }
    const uint32_t hiB = (uint32_t)(lg & 1) * 16;

    auto load_stage = [&](int t, int st) {
        const uint32_t sa = sb + (uint32_t)st * GT_STAGE;
        const int kf = t << 6;
#pragma unroll
        for (int i = 0; i < 2; i++) {
            int q = tid + i * 256;
            int row = q >> 3, ch = q & 7;
            cp16s(sa + (uint32_t)row * 128 + (uint32_t)((ch ^ (row & 7)) * 16),
                  A + (m0 + row) * (size_t)K + kf + ch * 8);
        }
#pragma unroll
        for (int i = 0; i < 6; i++) {
            int q = tid + i * 256;
            int row = q >> 3, ch = q & 7;
            cp16s(sa + GT_BOFF + (uint32_t)row * 128 + (uint32_t)((ch ^ (row & 7)) * 16),
                  BT + (size_t)(n0 + row) * K + kf + ch * 8);
        }
    };

    load_stage(0, 0);
    asm volatile("cp.async.commit_group;");
    load_stage(1, 1);
    asm volatile("cp.async.commit_group;");

    for (int t = 0; t < T; t++) {
        if (t + 2 < T) load_stage(t + 2, (t + 2) % 3);
        asm volatile("cp.async.commit_group;");
        asm volatile("cp.async.wait_group 2;");
        __syncthreads();

        const uint32_t sa  = sb + (uint32_t)(t % 3) * GT_STAGE;
        const uint32_t sbB = sa + GT_BOFF;
#pragma unroll
        for (int s = 0; s < 4; s++) {
            const uint32_t cs = (uint32_t)(s * 32);
            uint32_t a[2][4], b[6][2];
#pragma unroll
            for (int mi = 0; mi < 2; mi++)
                ldsm4(a[mi], sa + pA[mi] + ((cs + hiA) ^ xA[mi]));
#pragma unroll
            for (int p = 0; p < 3; p++) {
                uint32_t r[4];
                ldsm4(r, sbB + pB[p] + ((cs + hiB) ^ xB[p]));
                b[2 * p][0]     = r[0]; b[2 * p][1]     = r[1];
                b[2 * p + 1][0] = r[2]; b[2 * p + 1][1] = r[3];
            }
#pragma unroll
            for (int mi = 0; mi < 2; mi++)
#pragma unroll
                for (int nj = 0; nj < 6; nj++)
                    mma_f16(acc[mi][nj], a[mi], b[nj]);
        }
        __syncthreads();
    }

#pragma unroll
    for (int mi = 0; mi < 2; mi++) {
#pragma unroll
        for (int half = 0; half < 2; half++) {
            long r = m0 + wm * 32 + mi * 16 + g + half * 8;
#pragma unroll
            for (int nj = 0; nj < 6; nj++) {
                int cb = n0 + wn * 48 + nj * 8 + 2 * t4;
                float o0 = acc[mi][nj][half * 2 + 0] + __ldg(bias + cb);
                float o1 = acc[mi][nj][half * 2 + 1] + __ldg(bias + cb + 1);
                if (EPI == 1) {
                    o0 = 0.5f * o0 * (1.0f + erff(o0 * 0.7071067811865476f));
                    o1 = 0.5f * o1 * (1.0f + erff(o1 * 0.7071067811865476f));
                }
                if (EPI == 2 || EPI == 3) {
                    const float2 rv = *(const float2*)(res + r * (size_t)N + cb);
                    o0 += rv.x; o1 += rv.y;
                }
                if (EPI == 2) {
                    *(float2*)((float*)Cout + r * (size_t)N + cb) = make_float2(o0, o1);
                } else {
                    __half2 hv = __floats2half2_rn(o0, o1);
                    *(__half2*)((__half*)Cout + r * (size_t)N + cb) = hv;
                }
            }
        }
    }
}

// ---------------- Windowed attention: tensor cores + register softmax + bias table ----
#define AP 40
#define PP 72
#define BP 72   // bias smem pitch in halves (144B rows: bank stride g*4, conflict-free)

__global__ void __launch_bounds__(128, 6) attn_kernel(const __half* __restrict__ biasx)
{
    __shared__ __half qs[64 * AP];
    __shared__ __half ks[64 * AP];
    __shared__ __half vs[64 * AP];
    __shared__ __half P [64 * PP];
    __shared__ __half biasS[49 * BP];
    __shared__ int    grow[49];

    const int tid = threadIdx.x;
    const int w   = tid >> 5, lane = tid & 31;
    const int g   = lane >> 2, t4 = lane & 3;
    const int lg  = lane >> 3, lr = lane & 7;
    const int wid = blockIdx.x;
    const int h   = blockIdx.y;
    const int b   = wid >> 6;
    const int wr  = wid & 63;
    const int wy  = wr >> 3, wx = wr & 7;

    const uint32_t qsb = smem_u32(qs), ksb = smem_u32(ks), vsb = smem_u32(vs);
    const uint32_t Pb  = smem_u32(P),  bsb = smem_u32(biasS);

    if (tid < 49) {
        int ty = tid / 7, tx = tid - ty * 7;
        grow[tid] = b * 3136 + (wy * 7 + ty) * HW + (wx * 7 + tx);
    }
    // zero ks+vs pad rows 49..63 (S pad cols must be 0 before -65504 bias mask;
    // P*V pad-row hazard for vs). qs pads unused (pad softmax rows skipped).
    {
        uint32_t* zk = (uint32_t*)ks;
        uint32_t* zv = (uint32_t*)vs;
        for (int i = tid; i < 300; i += 128) { zk[980 + i] = 0; zv[980 + i] = 0; }
    }
    __syncthreads();

    // gather qkv + bias table
    for (int i = tid; i < 588; i += 128) {
        int t = i / 12;
        int rm = i - t * 12;
        int tensor = rm >> 2, ch = rm & 3;
        const __half* src = g_qkv + (size_t)grow[t] * QKVN + h * 96 + tensor * 32 + ch * 8;
        uint32_t base = (tensor == 0) ? qsb : (tensor == 1) ? ksb : vsb;
        cp16s(base + (uint32_t)t * 80 + (uint32_t)ch * 16, src);
    }
    for (int i = tid; i < 392; i += 128) {            // 49 rows x 8 chunks
        int row = i >> 3, ch = i & 7;
        cp16s(bsb + (uint32_t)row * 144 + (uint32_t)ch * 16,
              biasx + h * 3136 + row * 64 + ch * 8);
    }
    asm volatile("cp.async.commit_group;");
    asm volatile("cp.async.wait_group 0;");
    __syncthreads();

    // ---- S = Q K^T ----
    float acc[8][4];
#pragma unroll
    for (int nj = 0; nj < 8; nj++)
#pragma unroll
        for (int r = 0; r < 4; r++) acc[nj][r] = 0.f;

    const uint32_t aaddr = qsb + (uint32_t)(w * 16 + (lg & 1) * 8 + lr) * 80 + (uint32_t)(lg >> 1) * 16;
    const uint32_t baddr = ksb + (uint32_t)(((lg >> 1) & 1) * 8 + lr) * 80 + (uint32_t)(lg & 1) * 16;
#pragma unroll
    for (int s = 0; s < 2; s++) {
        uint32_t a[4];
        ldsm4(a, aaddr + s * 32);
#pragma unroll
        for (int p = 0; p < 4; p++) {
            uint32_t r[4];
            ldsm4(r, baddr + (uint32_t)p * (16 * 80) + s * 32);
            uint32_t b0[2] = {r[0], r[1]}, b1[2] = {r[2], r[3]};
            mma_f16(acc[2 * p], a, b0);
            mma_f16(acc[2 * p + 1], a, b1);
        }
    }

    // ---- softmax in registers (valid rows only; bias table has pad-col mask) ----
    const float scale = 0.17677669529663687f;
    const unsigned qmask = 0xFu << (lane & ~3);      // quad mask (quad lanes converged)
#pragma unroll
    for (int hh = 0; hh < 2; hh++) {
        const int rr = w * 16 + g + hh * 8;
        if (rr < 49) {
            float v[16];
            float mx = -1e30f;
#pragma unroll
            for (int nj = 0; nj < 8; nj++) {
                float2 bf = __half22float2(
                    *(const __half2*)(biasS + rr * BP + nj * 8 + 2 * t4));
                float v0 = acc[nj][hh * 2 + 0] * scale + bf.x;
                float v1 = acc[nj][hh * 2 + 1] * scale + bf.y;
                v[nj * 2]     = v0;
                v[nj * 2 + 1] = v1;
                mx = fmaxf(mx, fmaxf(v0, v1));
            }
            mx = fmaxf(mx, __shfl_xor_sync(qmask, mx, 1));
            mx = fmaxf(mx, __shfl_xor_sync(qmask, mx, 2));
            float sum = 0.f;
#pragma unroll
            for (int i = 0; i < 16; i++) { v[i] = __expf(v[i] - mx); sum += v[i]; }
            sum += __shfl_xor_sync(qmask, sum, 1);
            sum += __shfl_xor_sync(qmask, sum, 2);
            const float inv = 1.0f / sum;
#pragma unroll
            for (int nj = 0; nj < 8; nj++) {
                __half2 hv = __floats2half2_rn(v[nj * 2] * inv, v[nj * 2 + 1] * inv);
                *(__half2*)((__half*)P + rr * PP + nj * 8 + 2 * t4) = hv;
            }
        }
    }
    __syncthreads();

    // ---- O = P V ----
    float acc2[4][4];
#pragma unroll
    for (int nj = 0; nj < 4; nj++)
#pragma unroll
        for (int r = 0; r < 4; r++) acc2[nj][r] = 0.f;

    const uint32_t paddr = Pb + (uint32_t)(w * 16 + (lg & 1) * 8 + lr) * 144 + (uint32_t)(lg >> 1) * 16;
    const uint32_t vaddr = vsb + (uint32_t)((lg & 1) * 8 + lr) * 80 + (uint32_t)(lg >> 1) * 16;
#pragma unroll
    for (int s = 0; s < 4; s++) {
        uint32_t a[4];
        ldsm4(a, paddr + s * 32);
        uint32_t r0[4], r1[4];
        ldsm4t(r0, vaddr + (uint32_t)s * (16 * 80));
        ldsm4t(r1, vaddr + (uint32_t)s * (16 * 80) + 32);
        uint32_t b0[2] = {r0[0], r0[1]}, b1[2] = {r0[2], r0[3]};
        uint32_t b2[2] = {r1[0], r1[1]}, b3[2] = {r1[2], r1[3]};
        mma_f16(acc2[0], a, b0);
        mma_f16(acc2[1], a, b1);
        mma_f16(acc2[2], a, b2);
        mma_f16(acc2[3], a, b3);
    }

#pragma unroll
    for (int hh = 0; hh < 2; hh++) {
        int rr = w * 16 + g + hh * 8;
        if (rr < 49) {
            __half* orow = g_attn + (size_t)grow[rr] * CDIM + h * KD;
#pragma unroll
            for (int nj = 0; nj < 4; nj++) {
                int d = nj * 8 + 2 * t4;
                *(__half2*)(orow + d) =
                    __floats2half2_rn(acc2[nj][hh * 2 + 0], acc2[nj][hh * 2 + 1]);
            }
        }
    }
}

// ---------------- fused depthwise 3x3 conv + BN + LN2, 4 pixels/block (fp16 x1 in) ----
__global__ void __launch_bounds__(192) dwconv_bn_ln_kernel(const float* __restrict__ w,
                                                           const float* __restrict__ bg,
                                                           const float* __restrict__ bb,
                                                           const float* __restrict__ bmean,
                                                           const float* __restrict__ bvar,
                                                           const float* __restrict__ g2,
                                                           const float* __restrict__ b2)
{
    __shared__ float red[6][4];
    const int bid = blockIdx.x;
    const int cg  = bid % 14;
    const int tmp = bid / 14;
    const int r   = tmp % HW;
    const int bbi = tmp / HW;
    const int c0  = cg * 4;
    const int ch  = threadIdx.x;
    const int wd  = ch >> 5, lane = ch & 31;

    float w9[9];
#pragma unroll
    for (int i = 0; i < 9; i++) w9[i] = w[ch * 9 + i];

    float acc[4] = {0.f, 0.f, 0.f, 0.f};
#pragma unroll
    for (int kh = 0; kh < 3; kh++) {
        int rr = r + kh - 1;
        if (rr < 0 || rr >= HW) continue;
        const __half* rowb = g_x1 + ((size_t)bbi * 3136 + rr * HW) * CDIM + ch;
        float vals[6];
#pragma unroll
        for (int j = 0; j < 6; j++) {
            int col = c0 - 1 + j;
            vals[j] = (col >= 0 && col < HW) ? __half2float(rowb[(size_t)col * CDIM]) : 0.f;
        }
#pragma unroll
        for (int p = 0; p < 4; p++)
#pragma unroll
            for (int kw = 0; kw < 3; kw++)
                acc[p] += vals[p + kw] * w9[kh * 3 + kw];
    }

    const float inv = rsqrtf(bvar[ch] + 1e-5f);
    const float sc  = bg[ch] * inv;
    const float mu  = bmean[ch];
    const float bt  = bb[ch];
    float bnv[4];
#pragma unroll
    for (int p = 0; p < 4; p++) {
        bnv[p] = (acc[p] - mu) * sc + bt;
        g_x2[((size_t)bbi * 3136 + r * HW + c0 + p) * CDIM + ch] = bnv[p];
    }

    float s0 = bnv[0], s1 = bnv[1], s2 = bnv[2], s3 = bnv[3];
#pragma unroll
    for (int o = 16; o > 0; o >>= 1) {
        s0 += __shfl_xor_sync(0xffffffffu, s0, o);
        s1 += __shfl_xor_sync(0xffffffffu, s1, o);
        s2 += __shfl_xor_sync(0xffffffffu, s2, o);
        s3 += __shfl_xor_sync(0xffffffffu, s3, o);
    }
    if (lane == 0) { red[wd][0] = s0; red[wd][1] = s1; red[wd][2] = s2; red[wd][3] = s3; }
    __syncthreads();
    float mean[4];
#pragma unroll
    for (int p = 0; p < 4; p++)
        mean[p] = (red[0][p] + red[1][p] + red[2][p] + red[3][p] + red[4][p] + red[5][p]) * (1.0f / 192.0f);
    __syncthreads();

    float d[4];
    float q0, q1, q2, q3;
    d[0] = bnv[0] - mean[0]; q0 = d[0] * d[0];
    d[1] = bnv[1] - mean[1]; q1 = d[1] * d[1];
    d[2] = bnv[2] - mean[2]; q2 = d[2] * d[2];
    d[3] = bnv[3] - mean[3]; q3 = d[3] * d[3];
#pragma unroll
    for (int o = 16; o > 0; o >>= 1) {
        q0 += __shfl_xor_sync(0xffffffffu, q0, o);
        q1 += __shfl_xor_sync(0xffffffffu, q1, o);
        q2 += __shfl_xor_sync(0xffffffffu, q2, o);
        q3 += __shfl_xor_sync(0xffffffffu, q3, o);
    }
    if (lane == 0) { red[wd][0] = q0; red[wd][1] = q1; red[wd][2] = q2; red[wd][3] = q3; }
    __syncthreads();

    const float gg = g2[ch], b2v = b2[ch];
#pragma unroll
    for (int p = 0; p < 4; p++) {
        float var = (red[0][p] + red[1][p] + red[2][p] + red[3][p] + red[4][p] + red[5][p]) * (1.0f / 192.0f);
        float rstd = rsqrtf(var + 1e-5f);
        g_ln[((size_t)bbi * 3136 + r * HW + c0 + p) * CDIM + ch] =
            __float2half(d[p] * rstd * gg + b2v);
    }
}

// ---------------- launch ----------------
extern "C" void kernel_launch(void* const* d_in, const int* in_sizes, int n_in,
                              void* d_out, int out_size)
{
    (void)in_sizes; (void)n_in; (void)out_size;
    const float* x        = (const float*)d_in[0];
    const float* norm1_g  = (const float*)d_in[1];
    const float* norm1_b  = (const float*)d_in[2];
    const float* qkv_w    = (const float*)d_in[3];
    const float* qkv_b    = (const float*)d_in[4];
    const float* attnbias = (const float*)d_in[5];
    const float* proj_w   = (const float*)d_in[6];
    const float* proj_b   = (const float*)d_in[7];
    const float* conv_w   = (const float*)d_in[8];
    const float* bn_g     = (const float*)d_in[9];
    const float* bn_b     = (const float*)d_in[10];
    const float* bn_mean  = (const float*)d_in[11];
    const float* bn_var   = (const float*)d_in[12];
    const float* norm2_g  = (const float*)d_in[13];
    const float* norm2_b  = (const float*)d_in[14];
    const float* fc1_w    = (const float*)d_in[15];
    const float* fc1_b    = (const float*)d_in[16];
    const float* fc2_w    = (const float*)d_in[17];
    const float* fc2_b    = (const float*)d_in[18];
    float* out = (float*)d_out;

    __half *p_ln, *p_qkv, *p_attn, *p_mlp, *p_x1, *p_wt, *p_bx;
    float  *p_x2;
    cudaGetSymbolAddress((void**)&p_ln,   g_ln);
    cudaGetSymbolAddress((void**)&p_qkv,  g_qkv);
    cudaGetSymbolAddress((void**)&p_attn, g_attn);
    cudaGetSymbolAddress((void**)&p_mlp,  g_mlp);
    cudaGetSymbolAddress((void**)&p_x1,   g_x1);
    cudaGetSymbolAddress((void**)&p_x2,   g_x2);
    cudaGetSymbolAddress((void**)&p_wt,   g_wt);
    cudaGetSymbolAddress((void**)&p_bx,   g_biasx);

    cudaFuncSetAttribute(gemm_h<0>, cudaFuncAttributeMaxDynamicSharedMemorySize, GT_SMEM);
    cudaFuncSetAttribute(gemm_h<1>, cudaFuncAttributeMaxDynamicSharedMemorySize, GT_SMEM);
    cudaFuncSetAttribute(gemm_h<2>, cudaFuncAttributeMaxDynamicSharedMemorySize, GT_SMEM);
    cudaFuncSetAttribute(gemm_h<3>, cudaFuncAttributeMaxDynamicSharedMemorySize, GT_SMEM);

    // 1) prep: transposes + bias expansion + LN1
    prep_kernel<<<438 + MROWS / 8, 256>>>(qkv_w, proj_w, fc1_w, fc2_w, p_wt,
                                          attnbias, p_bx, x, norm1_g, norm1_b, p_ln);
    // 2) QKV GEMM
    gemm_h<0><<<dim3(MROWS / 64, QKVN / 192), 256, GT_SMEM>>>(p_ln, p_wt + W_QKV, qkv_b, nullptr, p_qkv, QKVN, CDIM);
    // 3) windowed attention (register softmax + bias table)
    attn_kernel<<<dim3(2048, NHEADS), 128>>>(p_bx);
    // 4) proj GEMM + residual x -> g_x1 (fp16)
    gemm_h<3><<<dim3(MROWS / 64, 1), 256, GT_SMEM>>>(p_attn, p_wt + W_PROJ, proj_b, x, p_x1, CDIM, CDIM);
    // 5) depthwise conv + BN + LN2 (fused, 4 px/block, fp16 x1)
    dwconv_bn_ln_kernel<<<32 * HW * (HW / 4), CDIM>>>(conv_w, bn_g, bn_b, bn_mean, bn_var, norm2_g, norm2_b);
    // 6) fc1 GEMM + GELU -> g_mlp (fp16)
    gemm_h<1><<<dim3(MROWS / 64, HID / 192), 256, GT_SMEM>>>(p_ln, p_wt + W_FC1, fc1_b, nullptr, p_mlp, HID, CDIM);
    // 7) fc2 GEMM + residual x2 -> out (f32)
    gemm_h<2><<<dim3(MROWS / 64, 1), 256, GT_SMEM>>>(p_mlp, p_wt + W_FC2, fc2_b, p_x2, out, CDIM, HID);
}

// round 16
// speedup vs baseline: 1.2895x; 1.1084x over previous
#include <cuda_runtime.h>
#include <cuda_fp16.h>
#include <math.h>
#include <stdint.h>

// ---------------- constants ----------------
#define MROWS  100352      // 32 * 3136
#define CDIM   192
#define NHEADS 6
#define KD     32
#define QKVN   576
#define HID    768
#define HW     56

// transposed fp16 weight scratch offsets (all [N,K] K-major)
#define W_QKV  0
#define W_PROJ 110592
#define W_FC1  147456
#define W_FC2  294912
#define W_TOT  442368

// ---------------- scratch ----------------
__device__ __half g_ln   [(size_t)MROWS * CDIM];
__device__ __half g_qkv  [(size_t)MROWS * QKVN];
__device__ __half g_attn [(size_t)MROWS * CDIM];
__device__ __half g_mlp  [(size_t)MROWS * HID];
__device__ __half g_x1   [(size_t)MROWS * CDIM];
__device__ __half g_x2   [(size_t)MROWS * CDIM];   // fp16 residual (R16)
__device__ __half g_wt   [W_TOT];
__device__ __half g_biasx[NHEADS * 49 * 64];       // expanded bias, cols>=49 = -65504

// ---------------- helpers ----------------
__device__ __forceinline__ uint32_t smem_u32(const void* p) {
    uint32_t a;
    asm("{ .reg .u64 t; cvta.to.shared.u64 t, %1; cvt.u32.u64 %0, t; }" : "=r"(a) : "l"(p));
    return a;
}

// L1-bypassing bulk copy: data is single-use, don't pollute/occupy L1
__device__ __forceinline__ void cp16s(uint32_t s, const void* g) {
    asm volatile("cp.async.cg.shared.global [%0], [%1], 16;" :: "r"(s), "l"(g));
}

__device__ __forceinline__ void ldsm4(uint32_t* r, uint32_t addr) {
    asm volatile("ldmatrix.sync.aligned.m8n8.x4.shared.b16 {%0,%1,%2,%3}, [%4];"
                 : "=r"(r[0]), "=r"(r[1]), "=r"(r[2]), "=r"(r[3]) : "r"(addr));
}

__device__ __forceinline__ void ldsm4t(uint32_t* r, uint32_t addr) {
    asm volatile("ldmatrix.sync.aligned.m8n8.x4.trans.shared.b16 {%0,%1,%2,%3}, [%4];"
                 : "=r"(r[0]), "=r"(r[1]), "=r"(r[2]), "=r"(r[3]) : "r"(addr));
}

__device__ __forceinline__ void mma_f16(float* d, const uint32_t* a, const uint32_t* b) {
    asm volatile(
        "mma.sync.aligned.m16n8k16.row.col.f32.f16.f16.f32 "
        "{%0,%1,%2,%3}, {%4,%5,%6,%7}, {%8,%9}, {%0,%1,%2,%3};"
        : "+f"(d[0]), "+f"(d[1]), "+f"(d[2]), "+f"(d[3])
        : "r"(a[0]), "r"(a[1]), "r"(a[2]), "r"(a[3]), "r"(b[0]), "r"(b[1]));
}

// ---------------- prep: weight transposes + bias expansion + LN1, one launch ----------
__global__ void __launch_bounds__(256) prep_kernel(const float* __restrict__ qkv_w,
                                                   const float* __restrict__ proj_w,
                                                   const float* __restrict__ fc1_w,
                                                   const float* __restrict__ fc2_w,
                                                   __half* __restrict__ wt,
                                                   const float* __restrict__ attn_bias,
                                                   __half* __restrict__ biasx,
                                                   const float* __restrict__ x,
                                                   const float* __restrict__ g1,
                                                   const float* __restrict__ b1,
                                                   __half* __restrict__ lnout)
{
    int bid = blockIdx.x;
    if (bid < 432) {
        __shared__ float t[32][33];
        const float* src; __half* dst; int Kdim, Ndim, bx, by;
        if (bid < 108)      { src = qkv_w;  dst = wt + W_QKV;  Kdim = CDIM; Ndim = QKVN; int q = bid;       bx = q % 18; by = q / 18; }
        else if (bid < 144) { src = proj_w; dst = wt + W_PROJ; Kdim = CDIM; Ndim = CDIM; int q = bid - 108; bx = q % 6;  by = q / 6; }
        else if (bid < 288) { src = fc1_w;  dst = wt + W_FC1;  Kdim = CDIM; Ndim = HID;  int q = bid - 144; bx = q % 24; by = q / 24; }
        else                { src = fc2_w;  dst = wt + W_FC2;  Kdim = HID;  Ndim = CDIM; int q = bid - 288; bx = q % 6;  by = q / 6; }

        int n0 = bx * 32, k0 = by * 32;
        int tx = threadIdx.x & 31, ty = threadIdx.x >> 5;
#pragma unroll
        for (int i = ty; i < 32; i += 8)
            t[i][tx] = src[(size_t)(k0 + i) * Ndim + n0 + tx];
        __syncthreads();
#pragma unroll
        for (int i = ty; i < 32; i += 8)
            dst[(size_t)(n0 + i) * Kdim + k0 + tx] = __float2half(t[tx][i]);
    } else if (bid < 438) {
        const int h = bid - 432;
        for (int i = threadIdx.x; i < 49 * 64; i += 256) {
            int n = i >> 6, m = i & 63;
            float v = -65504.f;
            if (m < 49) {
                int rn = n / 7, cn = n - rn * 7;
                int rm = m / 7, cm = m - rm * 7;
                v = attn_bias[h * 49 + abs(rn - rm) * 7 + abs(cn - cm)];
            }
            biasx[h * 3136 + i] = __float2half(v);
        }
    } else {
        int warp = threadIdx.x >> 5;
        int lane = threadIdx.x & 31;
        long row = (long)(bid - 438) * 8 + warp;
        const float* xr = x + row * CDIM;

        float v[6];
#pragma unroll
        for (int i = 0; i < 6; i++) v[i] = xr[lane + 32 * i];

        float s = 0.f;
#pragma unroll
        for (int i = 0; i < 6; i++) s += v[i];
#pragma unroll
        for (int o = 16; o > 0; o >>= 1) s += __shfl_xor_sync(0xffffffffu, s, o);
        float mean = s * (1.0f / 192.0f);

        float sq = 0.f;
#pragma unroll
        for (int i = 0; i < 6; i++) { float d = v[i] - mean; sq += d * d; }
#pragma unroll
        for (int o = 16; o > 0; o >>= 1) sq += __shfl_xor_sync(0xffffffffu, sq, o);
        float rstd = rsqrtf(sq * (1.0f / 192.0f) + 1e-5f);

        __half* orow = lnout + row * CDIM;
#pragma unroll
        for (int i = 0; i < 6; i++) {
            int c = lane + 32 * i;
            orow[c] = __float2half((v[i] - mean) * rstd * g1[c] + b1[c]);
        }
    }
}

// ---------------- FP16 mma GEMM: BM=64, BN=192, BK=64, 3-stage, 2 CTAs/SM ----------------
// EPI: 0 bias->fp16 | 1 bias+GELU->fp16 | 3 bias+res(f32)->fp16 | 4 bias+res(fp16)->f32
#define GT_BOFF  8192
#define GT_STAGE 32768
#define GT_SMEM  (3 * GT_STAGE)

template <int EPI>
__global__ void __launch_bounds__(256, 2) gemm_h(const __half* __restrict__ A,
                                                 const __half* __restrict__ BT,
                                                 const float* __restrict__ bias,
                                                 const void* __restrict__ res,
                                                 void* __restrict__ Cout,
                                                 int N, int K)
{
    extern __shared__ char smem[];
    const uint32_t sb = smem_u32(smem);

    const int tid  = threadIdx.x;
    const int wid  = tid >> 5, lane = tid & 31;
    const int wm   = wid & 1,  wn   = wid >> 1;
    const int g    = lane >> 2, t4  = lane & 3;
    const int lg   = lane >> 3, lr  = lane & 7;
    const long m0  = (long)blockIdx.x * 64;
    const int  n0  = blockIdx.y * 192;
    const int  T   = K >> 6;

    float acc[2][6][4];
#pragma unroll
    for (int mi = 0; mi < 2; mi++)
#pragma unroll
        for (int nj = 0; nj < 6; nj++)
#pragma unroll
            for (int r = 0; r < 4; r++) acc[mi][nj][r] = 0.f;

    uint32_t pA[2], xA[2];
#pragma unroll
    for (int mi = 0; mi < 2; mi++) {
        int row = wm * 32 + mi * 16 + (lg & 1) * 8 + lr;
        pA[mi] = (uint32_t)row * 128;
        xA[mi] = (uint32_t)(row & 7) * 16;
    }
    const uint32_t hiA = (uint32_t)(lg >> 1) * 16;
    uint32_t pB[3], xB[3];
#pragma unroll
    for (int p = 0; p < 3; p++) {
        int row = wn * 48 + p * 16 + ((lg >> 1) & 1) * 8 + lr;
        pB[p] = (uint32_t)row * 128;
        xB[p] = (uint32_t)(row & 7) * 16;
    }
    const uint32_t hiB = (uint32_t)(lg & 1) * 16;

    auto load_stage = [&](int t, int st) {
        const uint32_t sa = sb + (uint32_t)st * GT_STAGE;
        const int kf = t << 6;
#pragma unroll
        for (int i = 0; i < 2; i++) {
            int q = tid + i * 256;
            int row = q >> 3, ch = q & 7;
            cp16s(sa + (uint32_t)row * 128 + (uint32_t)((ch ^ (row & 7)) * 16),
                  A + (m0 + row) * (size_t)K + kf + ch * 8);
        }
#pragma unroll
        for (int i = 0; i < 6; i++) {
            int q = tid + i * 256;
            int row = q >> 3, ch = q & 7;
            cp16s(sa + GT_BOFF + (uint32_t)row * 128 + (uint32_t)((ch ^ (row & 7)) * 16),
                  BT + (size_t)(n0 + row) * K + kf + ch * 8);
        }
    };

    load_stage(0, 0);
    asm volatile("cp.async.commit_group;");
    load_stage(1, 1);
    asm volatile("cp.async.commit_group;");

    for (int t = 0; t < T; t++) {
        if (t + 2 < T) load_stage(t + 2, (t + 2) % 3);
        asm volatile("cp.async.commit_group;");
        asm volatile("cp.async.wait_group 2;");
        __syncthreads();

        const uint32_t sa  = sb + (uint32_t)(t % 3) * GT_STAGE;
        const uint32_t sbB = sa + GT_BOFF;
#pragma unroll
        for (int s = 0; s < 4; s++) {
            const uint32_t cs = (uint32_t)(s * 32);
            uint32_t a[2][4], b[6][2];
#pragma unroll
            for (int mi = 0; mi < 2; mi++)
                ldsm4(a[mi], sa + pA[mi] + ((cs + hiA) ^ xA[mi]));
#pragma unroll
            for (int p = 0; p < 3; p++) {
                uint32_t r[4];
                ldsm4(r, sbB + pB[p] + ((cs + hiB) ^ xB[p]));
                b[2 * p][0]     = r[0]; b[2 * p][1]     = r[1];
                b[2 * p + 1][0] = r[2]; b[2 * p + 1][1] = r[3];
            }
#pragma unroll
            for (int mi = 0; mi < 2; mi++)
#pragma unroll
                for (int nj = 0; nj < 6; nj++)
                    mma_f16(acc[mi][nj], a[mi], b[nj]);
        }
        __syncthreads();
    }

#pragma unroll
    for (int mi = 0; mi < 2; mi++) {
#pragma unroll
        for (int half = 0; half < 2; half++) {
            long r = m0 + wm * 32 + mi * 16 + g + half * 8;
#pragma unroll
            for (int nj = 0; nj < 6; nj++) {
                int cb = n0 + wn * 48 + nj * 8 + 2 * t4;
                float o0 = acc[mi][nj][half * 2 + 0] + __ldg(bias + cb);
                float o1 = acc[mi][nj][half * 2 + 1] + __ldg(bias + cb + 1);
                if (EPI == 1) {
                    o0 = 0.5f * o0 * (1.0f + erff(o0 * 0.7071067811865476f));
                    o1 = 0.5f * o1 * (1.0f + erff(o1 * 0.7071067811865476f));
                }
                if (EPI == 3) {
                    const float2 rv = *(const float2*)((const float*)res + r * (size_t)N + cb);
                    o0 += rv.x; o1 += rv.y;
                }
                if (EPI == 4) {
                    const float2 rv = __half22float2(
                        *(const __half2*)((const __half*)res + r * (size_t)N + cb));
                    o0 += rv.x; o1 += rv.y;
                }
                if (EPI == 4) {
                    *(float2*)((float*)Cout + r * (size_t)N + cb) = make_float2(o0, o1);
                } else {
                    __half2 hv = __floats2half2_rn(o0, o1);
                    *(__half2*)((__half*)Cout + r * (size_t)N + cb) = hv;
                }
            }
        }
    }
}

// ---------------- Windowed attention: tensor cores + register softmax + bias table ----
#define AP 40
#define PP 72
#define BP 72

__global__ void __launch_bounds__(128, 6) attn_kernel(const __half* __restrict__ biasx)
{
    __shared__ __half qs[64 * AP];
    __shared__ __half ks[64 * AP];
    __shared__ __half vs[64 * AP];
    __shared__ __half P [64 * PP];
    __shared__ __half biasS[49 * BP];
    __shared__ int    grow[49];

    const int tid = threadIdx.x;
    const int w   = tid >> 5, lane = tid & 31;
    const int g   = lane >> 2, t4 = lane & 3;
    const int lg  = lane >> 3, lr = lane & 7;
    const int wid = blockIdx.x;
    const int h   = blockIdx.y;
    const int b   = wid >> 6;
    const int wr  = wid & 63;
    const int wy  = wr >> 3, wx = wr & 7;

    const uint32_t qsb = smem_u32(qs), ksb = smem_u32(ks), vsb = smem_u32(vs);
    const uint32_t Pb  = smem_u32(P),  bsb = smem_u32(biasS);

    if (tid < 49) {
        int ty = tid / 7, tx = tid - ty * 7;
        grow[tid] = b * 3136 + (wy * 7 + ty) * HW + (wx * 7 + tx);
    }
    {
        uint32_t* zk = (uint32_t*)ks;
        uint32_t* zv = (uint32_t*)vs;
        for (int i = tid; i < 300; i += 128) { zk[980 + i] = 0; zv[980 + i] = 0; }
    }
    __syncthreads();

    for (int i = tid; i < 588; i += 128) {
        int t = i / 12;
        int rm = i - t * 12;
        int tensor = rm >> 2, ch = rm & 3;
        const __half* src = g_qkv + (size_t)grow[t] * QKVN + h * 96 + tensor * 32 + ch * 8;
        uint32_t base = (tensor == 0) ? qsb : (tensor == 1) ? ksb : vsb;
        cp16s(base + (uint32_t)t * 80 + (uint32_t)ch * 16, src);
    }
    for (int i = tid; i < 392; i += 128) {
        int row = i >> 3, ch = i & 7;
        cp16s(bsb + (uint32_t)row * 144 + (uint32_t)ch * 16,
              biasx + h * 3136 + row * 64 + ch * 8);
    }
    asm volatile("cp.async.commit_group;");
    asm volatile("cp.async.wait_group 0;");
    __syncthreads();

    float acc[8][4];
#pragma unroll
    for (int nj = 0; nj < 8; nj++)
#pragma unroll
        for (int r = 0; r < 4; r++) acc[nj][r] = 0.f;

    const uint32_t aaddr = qsb + (uint32_t)(w * 16 + (lg & 1) * 8 + lr) * 80 + (uint32_t)(lg >> 1) * 16;
    const uint32_t baddr = ksb + (uint32_t)(((lg >> 1) & 1) * 8 + lr) * 80 + (uint32_t)(lg & 1) * 16;
#pragma unroll
    for (int s = 0; s < 2; s++) {
        uint32_t a[4];
        ldsm4(a, aaddr + s * 32);
#pragma unroll
        for (int p = 0; p < 4; p++) {
            uint32_t r[4];
            ldsm4(r, baddr + (uint32_t)p * (16 * 80) + s * 32);
            uint32_t b0[2] = {r[0], r[1]}, b1[2] = {r[2], r[3]};
            mma_f16(acc[2 * p], a, b0);
            mma_f16(acc[2 * p + 1], a, b1);
        }
    }

    const float scale = 0.17677669529663687f;
    const unsigned qmask = 0xFu << (lane & ~3);
#pragma unroll
    for (int hh = 0; hh < 2; hh++) {
        const int rr = w * 16 + g + hh * 8;
        if (rr < 49) {
            float v[16];
            float mx = -1e30f;
#pragma unroll
            for (int nj = 0; nj < 8; nj++) {
                float2 bf = __half22float2(
                    *(const __half2*)(biasS + rr * BP + nj * 8 + 2 * t4));
                float v0 = acc[nj][hh * 2 + 0] * scale + bf.x;
                float v1 = acc[nj][hh * 2 + 1] * scale + bf.y;
                v[nj * 2]     = v0;
                v[nj * 2 + 1] = v1;
                mx = fmaxf(mx, fmaxf(v0, v1));
            }
            mx = fmaxf(mx, __shfl_xor_sync(qmask, mx, 1));
            mx = fmaxf(mx, __shfl_xor_sync(qmask, mx, 2));
            float sum = 0.f;
#pragma unroll
            for (int i = 0; i < 16; i++) { v[i] = __expf(v[i] - mx); sum += v[i]; }
            sum += __shfl_xor_sync(qmask, sum, 1);
            sum += __shfl_xor_sync(qmask, sum, 2);
            const float inv = 1.0f / sum;
#pragma unroll
            for (int nj = 0; nj < 8; nj++) {
                __half2 hv = __floats2half2_rn(v[nj * 2] * inv, v[nj * 2 + 1] * inv);
                *(__half2*)((__half*)P + rr * PP + nj * 8 + 2 * t4) = hv;
            }
        }
    }
    __syncthreads();

    float acc2[4][4];
#pragma unroll
    for (int nj = 0; nj < 4; nj++)
#pragma unroll
        for (int r = 0; r < 4; r++) acc2[nj][r] = 0.f;

    const uint32_t paddr = Pb + (uint32_t)(w * 16 + (lg & 1) * 8 + lr) * 144 + (uint32_t)(lg >> 1) * 16;
    const uint32_t vaddr = vsb + (uint32_t)((lg & 1) * 8 + lr) * 80 + (uint32_t)(lg >> 1) * 16;
#pragma unroll
    for (int s = 0; s < 4; s++) {
        uint32_t a[4];
        ldsm4(a, paddr + s * 32);
        uint32_t r0[4], r1[4];
        ldsm4t(r0, vaddr + (uint32_t)s * (16 * 80));
        ldsm4t(r1, vaddr + (uint32_t)s * (16 * 80) + 32);
        uint32_t b0[2] = {r0[0], r0[1]}, b1[2] = {r0[2], r0[3]};
        uint32_t b2[2] = {r1[0], r1[1]}, b3[2] = {r1[2], r1[3]};
        mma_f16(acc2[0], a, b0);
        mma_f16(acc2[1], a, b1);
        mma_f16(acc2[2], a, b2);
        mma_f16(acc2[3], a, b3);
    }

#pragma unroll
    for (int hh = 0; hh < 2; hh++) {
        int rr = w * 16 + g + hh * 8;
        if (rr < 49) {
            __half* orow = g_attn + (size_t)grow[rr] * CDIM + h * KD;
#pragma unroll
            for (int nj = 0; nj < 4; nj++) {
                int d = nj * 8 + 2 * t4;
                *(__half2*)(orow + d) =
                    __floats2half2_rn(acc2[nj][hh * 2 + 0], acc2[nj][hh * 2 + 1]);
            }
        }
    }
}

// ---------------- fused depthwise 3x3 conv + BN + LN2, 4 pixels/block (fp16 in/out) ----
__global__ void __launch_bounds__(192) dwconv_bn_ln_kernel(const float* __restrict__ w,
                                                           const float* __restrict__ bg,
                                                           const float* __restrict__ bb,
                                                           const float* __restrict__ bmean,
                                                           const float* __restrict__ bvar,
                                                           const float* __restrict__ g2,
                                                           const float* __restrict__ b2)
{
    __shared__ float red[6][4];
    const int bid = blockIdx.x;
    const int cg  = bid % 14;
    const int tmp = bid / 14;
    const int r   = tmp % HW;
    const int bbi = tmp / HW;
    const int c0  = cg * 4;
    const int ch  = threadIdx.x;
    const int wd  = ch >> 5, lane = ch & 31;

    float w9[9];
#pragma unroll
    for (int i = 0; i < 9; i++) w9[i] = w[ch * 9 + i];

    float acc[4] = {0.f, 0.f, 0.f, 0.f};
#pragma unroll
    for (int kh = 0; kh < 3; kh++) {
        int rr = r + kh - 1;
        if (rr < 0 || rr >= HW) continue;
        const __half* rowb = g_x1 + ((size_t)bbi * 3136 + rr * HW) * CDIM + ch;
        float vals[6];
#pragma unroll
        for (int j = 0; j < 6; j++) {
            int col = c0 - 1 + j;
            vals[j] = (col >= 0 && col < HW) ? __half2float(rowb[(size_t)col * CDIM]) : 0.f;
        }
#pragma unroll
        for (int p = 0; p < 4; p++)
#pragma unroll
            for (int kw = 0; kw < 3; kw++)
                acc[p] += vals[p + kw] * w9[kh * 3 + kw];
    }

    const float inv = rsqrtf(bvar[ch] + 1e-5f);
    const float sc  = bg[ch] * inv;
    const float mu  = bmean[ch];
    const float bt  = bb[ch];
    float bnv[4];
#pragma unroll
    for (int p = 0; p < 4; p++) {
        bnv[p] = (acc[p] - mu) * sc + bt;
        g_x2[((size_t)bbi * 3136 + r * HW + c0 + p) * CDIM + ch] = __float2half(bnv[p]);
    }

    float s0 = bnv[0], s1 = bnv[1], s2 = bnv[2], s3 = bnv[3];
#pragma unroll
    for (int o = 16; o > 0; o >>= 1) {
        s0 += __shfl_xor_sync(0xffffffffu, s0, o);
        s1 += __shfl_xor_sync(0xffffffffu, s1, o);
        s2 += __shfl_xor_sync(0xffffffffu, s2, o);
        s3 += __shfl_xor_sync(0xffffffffu, s3, o);
    }
    if (lane == 0) { red[wd][0] = s0; red[wd][1] = s1; red[wd][2] = s2; red[wd][3] = s3; }
    __syncthreads();
    float mean[4];
#pragma unroll
    for (int p = 0; p < 4; p++)
        mean[p] = (red[0][p] + red[1][p] + red[2][p] + red[3][p] + red[4][p] + red[5][p]) * (1.0f / 192.0f);
    __syncthreads();

    float d[4];
    float q0, q1, q2, q3;
    d[0] = bnv[0] - mean[0]; q0 = d[0] * d[0];
    d[1] = bnv[1] - mean[1]; q1 = d[1] * d[1];
    d[2] = bnv[2] - mean[2]; q2 = d[2] * d[2];
    d[3] = bnv[3] - mean[3]; q3 = d[3] * d[3];
#pragma unroll
    for (int o = 16; o > 0; o >>= 1) {
        q0 += __shfl_xor_sync(0xffffffffu, q0, o);
        q1 += __shfl_xor_sync(0xffffffffu, q1, o);
        q2 += __shfl_xor_sync(0xffffffffu, q2, o);
        q3 += __shfl_xor_sync(0xffffffffu, q3, o);
    }
    if (lane == 0) { red[wd][0] = q0; red[wd][1] = q1; red[wd][2] = q2; red[wd][3] = q3; }
    __syncthreads();

    const float gg = g2[ch], b2v = b2[ch];
#pragma unroll
    for (int p = 0; p < 4; p++) {
        float var = (red[0][p] + red[1][p] + red[2][p] + red[3][p] + red[4][p] + red[5][p]) * (1.0f / 192.0f);
        float rstd = rsqrtf(var + 1e-5f);
        g_ln[((size_t)bbi * 3136 + r * HW + c0 + p) * CDIM + ch] =
            __float2half(d[p] * rstd * gg + b2v);
    }
}

// ---------------- launch ----------------
extern "C" void kernel_launch(void* const* d_in, const int* in_sizes, int n_in,
                              void* d_out, int out_size)
{
    (void)in_sizes; (void)n_in; (void)out_size;
    const float* x        = (const float*)d_in[0];
    const float* norm1_g  = (const float*)d_in[1];
    const float* norm1_b  = (const float*)d_in[2];
    const float* qkv_w    = (const float*)d_in[3];
    const float* qkv_b    = (const float*)d_in[4];
    const float* attnbias = (const float*)d_in[5];
    const float* proj_w   = (const float*)d_in[6];
    const float* proj_b   = (const float*)d_in[7];
    const float* conv_w   = (const float*)d_in[8];
    const float* bn_g     = (const float*)d_in[9];
    const float* bn_b     = (const float*)d_in[10];
    const float* bn_mean  = (const float*)d_in[11];
    const float* bn_var   = (const float*)d_in[12];
    const float* norm2_g  = (const float*)d_in[13];
    const float* norm2_b  = (const float*)d_in[14];
    const float* fc1_w    = (const float*)d_in[15];
    const float* fc1_b    = (const float*)d_in[16];
    const float* fc2_w    = (const float*)d_in[17];
    const float* fc2_b    = (const float*)d_in[18];
    float* out = (float*)d_out;

    __half *p_ln, *p_qkv, *p_attn, *p_mlp, *p_x1, *p_x2, *p_wt, *p_bx;
    cudaGetSymbolAddress((void**)&p_ln,   g_ln);
    cudaGetSymbolAddress((void**)&p_qkv,  g_qkv);
    cudaGetSymbolAddress((void**)&p_attn, g_attn);
    cudaGetSymbolAddress((void**)&p_mlp,  g_mlp);
    cudaGetSymbolAddress((void**)&p_x1,   g_x1);
    cudaGetSymbolAddress((void**)&p_x2,   g_x2);
    cudaGetSymbolAddress((void**)&p_wt,   g_wt);
    cudaGetSymbolAddress((void**)&p_bx,   g_biasx);

    cudaFuncSetAttribute(gemm_h<0>, cudaFuncAttributeMaxDynamicSharedMemorySize, GT_SMEM);
    cudaFuncSetAttribute(gemm_h<1>, cudaFuncAttributeMaxDynamicSharedMemorySize, GT_SMEM);
    cudaFuncSetAttribute(gemm_h<3>, cudaFuncAttributeMaxDynamicSharedMemorySize, GT_SMEM);
    cudaFuncSetAttribute(gemm_h<4>, cudaFuncAttributeMaxDynamicSharedMemorySize, GT_SMEM);

    // 1) prep: transposes + bias expansion + LN1
    prep_kernel<<<438 + MROWS / 8, 256>>>(qkv_w, proj_w, fc1_w, fc2_w, p_wt,
                                          attnbias, p_bx, x, norm1_g, norm1_b, p_ln);
    // 2) QKV GEMM
    gemm_h<0><<<dim3(MROWS / 64, QKVN / 192), 256, GT_SMEM>>>(p_ln, p_wt + W_QKV, qkv_b, nullptr, p_qkv, QKVN, CDIM);
    // 3) windowed attention
    attn_kernel<<<dim3(2048, NHEADS), 128>>>(p_bx);
    // 4) proj GEMM + residual x (f32) -> g_x1 (fp16)
    gemm_h<3><<<dim3(MROWS / 64, 1), 256, GT_SMEM>>>(p_attn, p_wt + W_PROJ, proj_b, x, p_x1, CDIM, CDIM);
    // 5) depthwise conv + BN + LN2 (fused, 4 px/block)
    dwconv_bn_ln_kernel<<<32 * HW * (HW / 4), CDIM>>>(conv_w, bn_g, bn_b, bn_mean, bn_var, norm2_g, norm2_b);
    // 6) fc1 GEMM + GELU -> g_mlp (fp16)
    gemm_h<1><<<dim3(MROWS / 64, HID / 192), 256, GT_SMEM>>>(p_ln, p_wt + W_FC1, fc1_b, nullptr, p_mlp, HID, CDIM);
    // 7) fc2 GEMM + residual x2 (fp16) -> out (f32)
    gemm_h<4><<<dim3(MROWS / 64, 1), 256, GT_SMEM>>>(p_mlp, p_wt + W_FC2, fc2_b, p_x2, out, CDIM, HID);
}